// round 12
// baseline (speedup 1.0000x reference)
#include <cuda_runtime.h>
#include <cuda_fp16.h>
#include <math.h>
#include <stdint.h>

#define BATCH 4
#define SEQ   2048
#define DIM   1024
#define NHEAD 16
#define DH    64
#define NROWS (BATCH*SEQ)   // 8192

// ---------------- scratch (device globals) ----------------
__device__ __half g_Xh[(size_t)NROWS * DIM];
__device__ __half g_Xl[(size_t)NROWS * DIM];
__device__ __half g_Wh[(size_t)4 * DIM * DIM];
__device__ __half g_Wl[(size_t)4 * DIM * DIM];
__device__ __half g_Qh[(size_t)NROWS * DIM];
__device__ __half g_Ql[(size_t)NROWS * DIM];
__device__ __half g_Kh[(size_t)NROWS * DIM];
__device__ __half g_Kl[(size_t)NROWS * DIM];
__device__ __half g_Vh[(size_t)NROWS * DIM];
__device__ __half g_Vl[(size_t)NROWS * DIM];
__device__ __half g_Oh[(size_t)NROWS * DIM];
__device__ __half g_Ol[(size_t)NROWS * DIM];
__device__ float g_cos[SEQ * 32];
__device__ float g_sin[SEQ * 32];

// ---------------- helpers ----------------
__device__ __forceinline__ void splitf(float x, __half& h, __half& l) {
    h = __float2half_rn(x);
    l = __float2half_rn(x - __half2float(h));
}
__device__ __forceinline__ uint32_t pack2(__half a, __half b) {
    __half2 hh = __halves2half2(a, b);
    return *(uint32_t*)&hh;
}
__device__ __forceinline__ void mma16(float* c, const uint32_t* a, const uint32_t* b) {
    asm volatile(
        "mma.sync.aligned.m16n8k16.row.col.f32.f16.f16.f32 "
        "{%0,%1,%2,%3},{%4,%5,%6,%7},{%8,%9},{%0,%1,%2,%3};"
        : "+f"(c[0]), "+f"(c[1]), "+f"(c[2]), "+f"(c[3])
        : "r"(a[0]), "r"(a[1]), "r"(a[2]), "r"(a[3]), "r"(b[0]), "r"(b[1]));
}
__device__ __forceinline__ void ldmx4(uint32_t& d0, uint32_t& d1, uint32_t& d2, uint32_t& d3,
                                      uint32_t saddr) {
    asm volatile("ldmatrix.sync.aligned.m8n8.x4.shared.b16 {%0,%1,%2,%3}, [%4];"
                 : "=r"(d0), "=r"(d1), "=r"(d2), "=r"(d3) : "r"(saddr));
}
__device__ __forceinline__ void ldmx4t(uint32_t& d0, uint32_t& d1, uint32_t& d2, uint32_t& d3,
                                       uint32_t saddr) {
    asm volatile("ldmatrix.sync.aligned.m8n8.x4.trans.shared.b16 {%0,%1,%2,%3}, [%4];"
                 : "=r"(d0), "=r"(d1), "=r"(d2), "=r"(d3) : "r"(saddr));
}
__device__ __forceinline__ void cp16h(__half* dst, const __half* src) {
    unsigned s = (unsigned)__cvta_generic_to_shared(dst);
    asm volatile("cp.async.ca.shared.global [%0], [%1], 16;" :: "r"(s), "l"(src));
}
__device__ __forceinline__ void cp_commit() { asm volatile("cp.async.commit_group;"); }
template<int N>
__device__ __forceinline__ void cp_wait() { asm volatile("cp.async.wait_group %0;" :: "n"(N)); }

// ---------------- RoPE table ----------------
__global__ void rope_table_kernel(const int* __restrict__ pos)
{
    int idx = blockIdx.x * blockDim.x + threadIdx.x;
    if (idx >= SEQ * 32) return;
    int s = idx >> 5;
    int p = idx & 31;
    float inv = powf(10000.0f, -(float)(2 * p) / (float)DH);
    float ang = (float)pos[s] * inv;
    float sv, cv;
    sincosf(ang, &sv, &cv);
    g_cos[idx] = cv;
    g_sin[idx] = sv;
}

// ---------------- converters ----------------
__global__ void convert_x_kernel(const float* __restrict__ x)
{
    size_t i = ((size_t)blockIdx.x * blockDim.x + threadIdx.x) * 4;
    if (i >= (size_t)NROWS * DIM) return;
    float4 v = *(const float4*)(x + i);
    __half h0, l0, h1, l1, h2, l2, h3, l3;
    splitf(v.x, h0, l0); splitf(v.y, h1, l1);
    splitf(v.z, h2, l2); splitf(v.w, h3, l3);
    *(__half2*)&g_Xh[i]     = __halves2half2(h0, h1);
    *(__half2*)&g_Xh[i + 2] = __halves2half2(h2, h3);
    *(__half2*)&g_Xl[i]     = __halves2half2(l0, l1);
    *(__half2*)&g_Xl[i + 2] = __halves2half2(l2, l3);
}
__global__ void convert_w_all_kernel(const float* __restrict__ W0,
                                     const float* __restrict__ W1,
                                     const float* __restrict__ W2,
                                     const float* __restrict__ W3)
{
    int widx = blockIdx.y;
    const float* W = (widx == 0) ? W0 : (widx == 1) ? W1 : (widx == 2) ? W2 : W3;
    size_t i = ((size_t)blockIdx.x * blockDim.x + threadIdx.x) * 4;
    if (i >= (size_t)DIM * DIM) return;
    size_t o = (size_t)widx * DIM * DIM + i;
    float4 v = *(const float4*)(W + i);
    v.x *= 256.0f; v.y *= 256.0f; v.z *= 256.0f; v.w *= 256.0f;
    __half h0, l0, h1, l1, h2, l2, h3, l3;
    splitf(v.x, h0, l0); splitf(v.y, h1, l1);
    splitf(v.z, h2, l2); splitf(v.w, h3, l3);
    *(__half2*)&g_Wh[o]     = __halves2half2(h0, h1);
    *(__half2*)&g_Wh[o + 2] = __halves2half2(h2, h3);
    *(__half2*)&g_Wl[o]     = __halves2half2(l0, l1);
    *(__half2*)&g_Wl[o + 2] = __halves2half2(l2, l3);
}

// ---------------- fp16x2 GEMM: 4 warps x (64x64), 2-stage K32 (R10 exact) ----------------
// FUSED: blockIdx.z = mode (0=Q rope,1=K rope,2=V); !FUSED: mode 3, out-proj -> Cout
#define GKP 40
#define GPL (128 * GKP)
#define GSTG (4 * GPL)
#define GEMM_SMEM (2 * GSTG * 2)  // 81920 B

template<bool FUSED>
__global__ void __launch_bounds__(128, 2) gemm_h2(float* __restrict__ Cout)
{
    extern __shared__ __half smh[];
    const int mode = FUSED ? (int)blockIdx.z : 3;
    const __half* Aph = FUSED ? g_Xh : g_Oh;
    const __half* Apl = FUSED ? g_Xl : g_Ol;
    const __half* Bph = g_Wh + (size_t)mode * DIM * DIM;
    const __half* Bpl = g_Wl + (size_t)mode * DIM * DIM;
    const uint32_t sb = (uint32_t)__cvta_generic_to_shared(smh);

    const int tid  = threadIdx.x;
    const int lane = tid & 31;
    const int wid  = tid >> 5;    // 0..3
    const int g    = lane >> 2;
    const int t    = lane & 3;
    const int wm   = wid & 1;
    const int wn   = wid >> 1;

    const int row0 = blockIdx.y * 128;
    const int col0 = blockIdx.x * 128;

    const int a_r = ((lane >> 3) & 1) * 8 + (lane & 7);
    const int a_c = ((lane >> 4) & 1) * 8;
    const int b_rsel = (lane >> 4);
    const int b_r = (lane & 7);
    const int b_c = ((lane >> 3) & 1) * 8;

    float acc[4][8][4];
    #pragma unroll
    for (int im = 0; im < 4; im++)
        #pragma unroll
        for (int in = 0; in < 8; in++)
            #pragma unroll
            for (int e = 0; e < 4; e++)
                acc[im][in][e] = 0.0f;

    auto load_stage = [&](int st, int kt) {
        const int k0 = kt * 32;
        #pragma unroll
        for (int i = 0; i < 16; i++) {
            int uidx = tid + i * 128;
            int p    = uidx >> 9;
            int w    = uidx & 511;
            int row  = w >> 2;
            int un   = (w & 3) * 8;
            const __half* src;
            if (p == 0)      src = Aph + (size_t)(row0 + row) * DIM + k0 + un;
            else if (p == 1) src = Apl + (size_t)(row0 + row) * DIM + k0 + un;
            else if (p == 2) src = Bph + (size_t)(col0 + row) * DIM + k0 + un;
            else             src = Bpl + (size_t)(col0 + row) * DIM + k0 + un;
            cp16h(&smh[st * GSTG + p * GPL + row * GKP + un], src);
        }
    };

    load_stage(0, 0);
    cp_commit();

    const int NKT = DIM / 32;
    for (int kt = 0; kt < NKT; kt++) {
        const int st = kt & 1;
        cp_wait<0>();
        __syncthreads();
        if (kt + 1 < NKT) { load_stage(st ^ 1, kt + 1); cp_commit(); }

        const uint32_t s0 = sb + (uint32_t)(st * GSTG) * 2u;
        #pragma unroll
        for (int kq = 0; kq < 2; kq++) {
            const int kk = kq * 16;
            uint32_t bh[8][2], bl[8][2];
            #pragma unroll
            for (int q = 0; q < 4; q++) {
                uint32_t boff = (uint32_t)((wn * 64 + (2 * q + b_rsel) * 8 + b_r) * GKP
                                           + kk + b_c) * 2u;
                ldmx4(bh[2*q][0], bh[2*q][1], bh[2*q+1][0], bh[2*q+1][1],
                      s0 + (uint32_t)(2 * GPL) * 2u + boff);
                ldmx4(bl[2*q][0], bl[2*q][1], bl[2*q+1][0], bl[2*q+1][1],
                      s0 + (uint32_t)(3 * GPL) * 2u + boff);
            }
            #pragma unroll
            for (int im = 0; im < 4; im++) {
                uint32_t aoff = (uint32_t)((wm * 64 + im * 16 + a_r) * GKP + kk + a_c) * 2u;
                uint32_t ahi[4], alo[4];
                ldmx4(ahi[0], ahi[1], ahi[2], ahi[3], s0 + aoff);
                ldmx4(alo[0], alo[1], alo[2], alo[3], s0 + (uint32_t)GPL * 2u + aoff);
                #pragma unroll
                for (int in = 0; in < 8; in++) {
                    mma16(acc[im][in], ahi, bh[in]);
                    mma16(acc[im][in], ahi, bl[in]);
                    mma16(acc[im][in], alo, bh[in]);
                }
            }
        }
        __syncthreads();
    }

    const float sc = 1.0f / 256.0f;
    #pragma unroll
    for (int im = 0; im < 4; im++) {
        int r0 = row0 + wm * 64 + im * 16 + g;
        int r1 = r0 + 8;
        #pragma unroll
        for (int in = 0; in < 8; in++) {
            int c = col0 + wn * 64 + in * 8 + 2 * t;
            float v0 = acc[im][in][0] * sc, v1 = acc[im][in][1] * sc;
            float v2 = acc[im][in][2] * sc, v3 = acc[im][in][3] * sc;
            if (!FUSED) {
                float2 o0 = { v0, v1 };
                float2 o1 = { v2, v3 };
                *(float2*)(Cout + (size_t)r0 * DIM + c) = o0;
                *(float2*)(Cout + (size_t)r1 * DIM + c) = o1;
            } else {
                if (mode <= 1) {
                    int p = (c & 63) >> 1;
                    int s0i = r0 & (SEQ - 1);
                    int s1i = r1 & (SEQ - 1);
                    float cv0 = g_cos[s0i * 32 + p], sv0 = g_sin[s0i * 32 + p];
                    float cv1 = g_cos[s1i * 32 + p], sv1 = g_sin[s1i * 32 + p];
                    float n0 = v0 * cv0 - v1 * sv0, n1 = v0 * sv0 + v1 * cv0;
                    float n2 = v2 * cv1 - v3 * sv1, n3 = v2 * sv1 + v3 * cv1;
                    v0 = n0; v1 = n1; v2 = n2; v3 = n3;
                }
                __half* Ch = (mode == 0) ? g_Qh : (mode == 1) ? g_Kh : g_Vh;
                __half* Cl = (mode == 0) ? g_Ql : (mode == 1) ? g_Kl : g_Vl;
                __half h0, l0, h1, l1;
                splitf(v0, h0, l0); splitf(v1, h1, l1);
                *(__half2*)&Ch[(size_t)r0 * DIM + c] = __halves2half2(h0, h1);
                *(__half2*)&Cl[(size_t)r0 * DIM + c] = __halves2half2(l0, l1);
                splitf(v2, h0, l0); splitf(v3, h1, l1);
                *(__half2*)&Ch[(size_t)r1 * DIM + c] = __halves2half2(h0, h1);
                *(__half2*)&Cl[(size_t)r1 * DIM + c] = __halves2half2(l0, l1);
            }
        }
    }
}

// ---------------- flash attention: Q frags hoisted to registers ----------------
#define AKP 72
#define OQH 0
#define OQL (128 * AKP)
#define OKV0 (2 * 128 * AKP)
#define KVSTG (4 * 64 * AKP)
#define ATT_SMEM ((OKV0 + 2 * KVSTG) * 2)     // 110592 B
#define SCALE_LOG2E 0.1803368801111204f       // 0.125 * log2(e)

__global__ void __launch_bounds__(128, 2) attn_h2_kernel()
{
    extern __shared__ __half smh[];
    __half* qh = smh + OQH;  __half* ql = smh + OQL;
    const uint32_t sb = (uint32_t)__cvta_generic_to_shared(smh);

    const int tid  = threadIdx.x;
    const int lane = tid & 31;
    const int wid  = tid >> 5;
    const int g    = lane >> 2;
    const int t    = lane & 3;

    const int qt = (int)gridDim.x - 1 - (int)blockIdx.x;
    const int q0 = qt * 128;
    const int bh_ = blockIdx.y;
    const int b  = bh_ >> 4;
    const int h  = bh_ & 15;

    const size_t base = (size_t)b * SEQ * DIM + h * DH;
    const __half* Qhb = g_Qh + base;  const __half* Qlb = g_Ql + base;
    const __half* Khb = g_Kh + base;  const __half* Klb = g_Kl + base;
    const __half* Vhb = g_Vh + base;  const __half* Vlb = g_Vl + base;

    const int a_r = ((lane >> 3) & 1) * 8 + (lane & 7);
    const int a_c = ((lane >> 4) & 1) * 8;
    const int b_rsel = (lane >> 4);
    const int b_r = (lane & 7);
    const int b_c = ((lane >> 3) & 1) * 8;

    #pragma unroll
    for (int i = 0; i < 16; i++) {
        int pos = tid + i * 128;
        int pl_ = pos >> 10;
        int w   = pos & 1023;
        int row = w >> 3;
        int u   = (w & 7) * 8;
        const __half* src = (pl_ == 0) ? Qhb : Qlb;
        __half* dst = (pl_ == 0) ? qh : ql;
        *(uint4*)&dst[row * AKP + u] = *(const uint4*)(src + (size_t)(q0 + row) * DIM + u);
    }

    auto load_kv = [&](int st, int kvt) {
        const int kv0 = kvt * 64;
        __half* kvbase = smh + OKV0 + st * KVSTG;
        #pragma unroll
        for (int i = 0; i < 16; i++) {
            int uidx = tid + i * 128;
            int p    = uidx >> 9;
            int w    = uidx & 511;
            int row  = w >> 3;
            int u    = (w & 7) * 8;
            const __half* src;
            if (p == 0)      src = Khb;
            else if (p == 1) src = Klb;
            else if (p == 2) src = Vhb;
            else             src = Vlb;
            cp16h(&kvbase[p * 64 * AKP + row * AKP + u],
                  src + (size_t)(kv0 + row) * DIM + u);
        }
    };

    float o[2][8][4];
    float m[4], l[4];
    #pragma unroll
    for (int im = 0; im < 2; im++)
        #pragma unroll
        for (int n = 0; n < 8; n++)
            #pragma unroll
            for (int e = 0; e < 4; e++)
                o[im][n][e] = 0.0f;
    #pragma unroll
    for (int i = 0; i < 4; i++) { m[i] = -INFINITY; l[i] = 0.0f; }

    const int rb  = wid * 32;
    const int wq0 = q0 + rb;
    const int ntiles = 2 * qt + 2;

    load_kv(0, 0);
    cp_commit();
    __syncthreads();   // Q planes visible

    // ---- hoist Q A-fragments to registers (invariant across KV tiles) ----
    uint32_t qfh[4][2][4], qfl[4][2][4];
    #pragma unroll
    for (int ks = 0; ks < 4; ks++) {
        const int kk = ks * 16;
        #pragma unroll
        for (int im = 0; im < 2; im++) {
            uint32_t aoff = (uint32_t)((rb + im * 16 + a_r) * AKP + kk + a_c) * 2u;
            ldmx4(qfh[ks][im][0], qfh[ks][im][1], qfh[ks][im][2], qfh[ks][im][3],
                  sb + (uint32_t)(OQH * 2) + aoff);
            ldmx4(qfl[ks][im][0], qfl[ks][im][1], qfl[ks][im][2], qfl[ks][im][3],
                  sb + (uint32_t)(OQL * 2) + aoff);
        }
    }

    for (int kvt = 0; kvt < ntiles; kvt++) {
        const int st = kvt & 1;
        const int kv0 = kvt * 64;
        cp_wait<0>();
        __syncthreads();
        if (kvt + 1 < ntiles) { load_kv(st ^ 1, kvt + 1); cp_commit(); }

        const uint32_t kvb = sb + (uint32_t)(OKV0 + st * KVSTG) * 2u;
        const uint32_t khB = kvb;
        const uint32_t klB = kvb + (uint32_t)(64 * AKP) * 2u;
        const uint32_t vhB = kvb + (uint32_t)(2 * 64 * AKP) * 2u;
        const uint32_t vlB = kvb + (uint32_t)(3 * 64 * AKP) * 2u;

        const bool active = (kv0 <= wq0 + 31);
        if (active) {
            float s[2][8][4];
            #pragma unroll
            for (int im = 0; im < 2; im++)
                #pragma unroll
                for (int n = 0; n < 8; n++)
                    #pragma unroll
                    for (int e = 0; e < 4; e++)
                        s[im][n][e] = 0.0f;

            #pragma unroll
            for (int ks = 0; ks < 4; ks++) {
                const int kk = ks * 16;
                uint32_t bh[8][2], bl[8][2];
                #pragma unroll
                for (int q = 0; q < 4; q++) {
                    uint32_t boff = (uint32_t)(((2 * q + b_rsel) * 8 + b_r) * AKP
                                               + kk + b_c) * 2u;
                    ldmx4(bh[2*q][0], bh[2*q][1], bh[2*q+1][0], bh[2*q+1][1], khB + boff);
                    ldmx4(bl[2*q][0], bl[2*q][1], bl[2*q+1][0], bl[2*q+1][1], klB + boff);
                }
                #pragma unroll
                for (int im = 0; im < 2; im++)
                    #pragma unroll
                    for (int n = 0; n < 8; n++) {
                        mma16(s[im][n], qfh[ks][im], bh[n]);
                        mma16(s[im][n], qfh[ks][im], bl[n]);
                        mma16(s[im][n], qfl[ks][im], bh[n]);
                    }
            }

            // ---- scale (x log2e) + causal mask; softmax in exp2 domain ----
            const bool needmask = (kv0 + 63) > wq0;
            #pragma unroll
            for (int im = 0; im < 2; im++)
                #pragma unroll
                for (int n = 0; n < 8; n++)
                    #pragma unroll
                    for (int e = 0; e < 4; e++) {
                        float v = s[im][n][e] * SCALE_LOG2E;
                        if (needmask) {
                            int col = kv0 + n * 8 + 2 * t + (e & 1);
                            int row = wq0 + im * 16 + g + ((e >> 1) * 8);
                            if (col > row) v = -1e30f;
                        }
                        s[im][n][e] = v;
                    }

            #pragma unroll
            for (int im = 0; im < 2; im++) {
                #pragma unroll
                for (int hh = 0; hh < 2; hh++) {
                    int ri = im * 2 + hh;
                    float rowmax = -INFINITY;
                    #pragma unroll
                    for (int n = 0; n < 8; n++) {
                        rowmax = fmaxf(rowmax, s[im][n][hh * 2 + 0]);
                        rowmax = fmaxf(rowmax, s[im][n][hh * 2 + 1]);
                    }
                    rowmax = fmaxf(rowmax, __shfl_xor_sync(0xffffffffu, rowmax, 1));
                    rowmax = fmaxf(rowmax, __shfl_xor_sync(0xffffffffu, rowmax, 2));
                    float mnew = fmaxf(m[ri], rowmax);
                    float alpha = exp2f(m[ri] - mnew);
                    m[ri] = mnew;
                    float rs = 0.0f;
                    #pragma unroll
                    for (int n = 0; n < 8; n++) {
                        float p0 = exp2f(s[im][n][hh * 2 + 0] - mnew);
                        float p1 = exp2f(s[im][n][hh * 2 + 1] - mnew);
                        s[im][n][hh * 2 + 0] = p0;
                        s[im][n][hh * 2 + 1] = p1;
                        rs += p0 + p1;
                    }
                    rs += __shfl_xor_sync(0xffffffffu, rs, 1);
                    rs += __shfl_xor_sync(0xffffffffu, rs, 2);
                    l[ri] = l[ri] * alpha + rs;
                    #pragma unroll
                    for (int n = 0; n < 8; n++) {
                        o[im][n][hh * 2 + 0] *= alpha;
                        o[im][n][hh * 2 + 1] *= alpha;
                    }
                }
            }

            const int rml = ((lane >> 3) & 1) * 8 + (lane & 7);
            const int cml0 = (lane >> 4) * 8;
            #pragma unroll
            for (int ks = 0; ks < 4; ks++) {
                const int kk = ks * 16;
                uint32_t ahi[2][4], alo[2][4];
                #pragma unroll
                for (int im = 0; im < 2; im++) {
                    __half h0, l0_, h1, l1_;
                    splitf(s[im][2*ks][0] * 256.0f, h0, l0_);
                    splitf(s[im][2*ks][1] * 256.0f, h1, l1_);
                    ahi[im][0] = pack2(h0, h1);  alo[im][0] = pack2(l0_, l1_);
                    splitf(s[im][2*ks][2] * 256.0f, h0, l0_);
                    splitf(s[im][2*ks][3] * 256.0f, h1, l1_);
                    ahi[im][1] = pack2(h0, h1);  alo[im][1] = pack2(l0_, l1_);
                    splitf(s[im][2*ks+1][0] * 256.0f, h0, l0_);
                    splitf(s[im][2*ks+1][1] * 256.0f, h1, l1_);
                    ahi[im][2] = pack2(h0, h1);  alo[im][2] = pack2(l0_, l1_);
                    splitf(s[im][2*ks+1][2] * 256.0f, h0, l0_);
                    splitf(s[im][2*ks+1][3] * 256.0f, h1, l1_);
                    ahi[im][3] = pack2(h0, h1);  alo[im][3] = pack2(l0_, l1_);
                }
                #pragma unroll
                for (int nb = 0; nb < 4; nb++) {
                    uint32_t voff = (uint32_t)((kk + rml) * AKP + nb * 16 + cml0) * 2u;
                    uint32_t h0, h1, h2, h3, l0_, l1_, l2_, l3_;
                    ldmx4t(h0, h1, h2, h3, vhB + voff);
                    ldmx4t(l0_, l1_, l2_, l3_, vlB + voff);
                    uint32_t bh0[2] = { h0, h1 }, bh1[2] = { h2, h3 };
                    uint32_t bl0[2] = { l0_, l1_ }, bl1[2] = { l2_, l3_ };
                    #pragma unroll
                    for (int im = 0; im < 2; im++) {
                        mma16(o[im][2 * nb + 0], ahi[im], bh0);
                        mma16(o[im][2 * nb + 0], ahi[im], bl0);
                        mma16(o[im][2 * nb + 0], alo[im], bh0);
                        mma16(o[im][2 * nb + 1], ahi[im], bh1);
                        mma16(o[im][2 * nb + 1], ahi[im], bl1);
                        mma16(o[im][2 * nb + 1], alo[im], bh1);
                    }
                }
            }
        }
        __syncthreads();
    }

    __half* Ohb = g_Oh + base;
    __half* Olb = g_Ol + base;
    #pragma unroll
    for (int im = 0; im < 2; im++) {
        int r0 = q0 + rb + im * 16 + g;
        int r1 = r0 + 8;
        float inv0 = 1.0f / (256.0f * l[im * 2 + 0]);
        float inv1 = 1.0f / (256.0f * l[im * 2 + 1]);
        #pragma unroll
        for (int n = 0; n < 8; n++) {
            int c = n * 8 + 2 * t;
            __half h0, l0_, h1, l1_;
            splitf(o[im][n][0] * inv0, h0, l0_);
            splitf(o[im][n][1] * inv0, h1, l1_);
            *(__half2*)&Ohb[(size_t)r0 * DIM + c] = __halves2half2(h0, h1);
            *(__half2*)&Olb[(size_t)r0 * DIM + c] = __halves2half2(l0_, l1_);
            splitf(o[im][n][2] * inv1, h0, l0_);
            splitf(o[im][n][3] * inv1, h1, l1_);
            *(__half2*)&Ohb[(size_t)r1 * DIM + c] = __halves2half2(h0, h1);
            *(__half2*)&Olb[(size_t)r1 * DIM + c] = __halves2half2(l0_, l1_);
        }
    }
}

// ---------------- launch ----------------
extern "C" void kernel_launch(void* const* d_in, const int* in_sizes, int n_in,
                              void* d_out, int out_size)
{
    const float* x  = (const float*)d_in[0];
    const float* WQ = (const float*)d_in[1];
    const float* WK = (const float*)d_in[2];
    const float* WV = (const float*)d_in[3];
    const float* WO = (const float*)d_in[4];
    const int*  pos = (const int*)d_in[5];
    float* out = (float*)d_out;

    cudaFuncSetAttribute(gemm_h2<true>,  cudaFuncAttributeMaxDynamicSharedMemorySize, GEMM_SMEM);
    cudaFuncSetAttribute(gemm_h2<false>, cudaFuncAttributeMaxDynamicSharedMemorySize, GEMM_SMEM);
    cudaFuncSetAttribute(attn_h2_kernel, cudaFuncAttributeMaxDynamicSharedMemorySize, ATT_SMEM);

    rope_table_kernel<<<(SEQ * 32 + 255) / 256, 256>>>(pos);
    convert_x_kernel<<<(NROWS * DIM / 4 + 255) / 256, 256>>>(x);
    convert_w_all_kernel<<<dim3((DIM * DIM / 4 + 255) / 256, 4), 256>>>(WQ, WK, WV, WO);

    gemm_h2<true><<<dim3(DIM / 128, NROWS / 128, 3), 128, GEMM_SMEM>>>(nullptr);

    attn_h2_kernel<<<dim3(SEQ / 128, BATCH * NHEAD), 128, ATT_SMEM>>>();

    gemm_h2<false><<<dim3(DIM / 128, NROWS / 128, 1), 128, GEMM_SMEM>>>(out);
}

// round 13
// speedup vs baseline: 1.0681x; 1.0681x over previous
#include <cuda_runtime.h>
#include <cuda_fp16.h>
#include <math.h>
#include <stdint.h>

#define BATCH 4
#define SEQ   2048
#define DIM   1024
#define NHEAD 16
#define DH    64
#define NROWS (BATCH*SEQ)   // 8192

// ---------------- scratch (device globals) ----------------
__device__ __half g_Xh[(size_t)NROWS * DIM];
__device__ __half g_Xl[(size_t)NROWS * DIM];
__device__ __half g_Wh[(size_t)4 * DIM * DIM];
__device__ __half g_Wl[(size_t)4 * DIM * DIM];
__device__ __half g_Qh[(size_t)NROWS * DIM];
__device__ __half g_Ql[(size_t)NROWS * DIM];
__device__ __half g_Kh[(size_t)NROWS * DIM];
__device__ __half g_Kl[(size_t)NROWS * DIM];
__device__ __half g_Vh[(size_t)NROWS * DIM];
__device__ __half g_Vl[(size_t)NROWS * DIM];
__device__ __half g_Oh[(size_t)NROWS * DIM];
__device__ __half g_Ol[(size_t)NROWS * DIM];
__device__ float g_cos[SEQ * 32];
__device__ float g_sin[SEQ * 32];

// ---------------- helpers ----------------
__device__ __forceinline__ void splitf(float x, __half& h, __half& l) {
    h = __float2half_rn(x);
    l = __float2half_rn(x - __half2float(h));
}
__device__ __forceinline__ uint32_t pack2(__half a, __half b) {
    __half2 hh = __halves2half2(a, b);
    return *(uint32_t*)&hh;
}
__device__ __forceinline__ void mma16(float* c, const uint32_t* a, const uint32_t* b) {
    asm volatile(
        "mma.sync.aligned.m16n8k16.row.col.f32.f16.f16.f32 "
        "{%0,%1,%2,%3},{%4,%5,%6,%7},{%8,%9},{%0,%1,%2,%3};"
        : "+f"(c[0]), "+f"(c[1]), "+f"(c[2]), "+f"(c[3])
        : "r"(a[0]), "r"(a[1]), "r"(a[2]), "r"(a[3]), "r"(b[0]), "r"(b[1]));
}
__device__ __forceinline__ void ldmx4(uint32_t& d0, uint32_t& d1, uint32_t& d2, uint32_t& d3,
                                      uint32_t saddr) {
    asm volatile("ldmatrix.sync.aligned.m8n8.x4.shared.b16 {%0,%1,%2,%3}, [%4];"
                 : "=r"(d0), "=r"(d1), "=r"(d2), "=r"(d3) : "r"(saddr));
}
__device__ __forceinline__ void ldmx4t(uint32_t& d0, uint32_t& d1, uint32_t& d2, uint32_t& d3,
                                       uint32_t saddr) {
    asm volatile("ldmatrix.sync.aligned.m8n8.x4.trans.shared.b16 {%0,%1,%2,%3}, [%4];"
                 : "=r"(d0), "=r"(d1), "=r"(d2), "=r"(d3) : "r"(saddr));
}
__device__ __forceinline__ void cp16h(__half* dst, const __half* src) {
    unsigned s = (unsigned)__cvta_generic_to_shared(dst);
    asm volatile("cp.async.ca.shared.global [%0], [%1], 16;" :: "r"(s), "l"(src));
}
__device__ __forceinline__ void cp_commit() { asm volatile("cp.async.commit_group;"); }
template<int N>
__device__ __forceinline__ void cp_wait() { asm volatile("cp.async.wait_group %0;" :: "n"(N)); }

// ---------------- RoPE table ----------------
__global__ void rope_table_kernel(const int* __restrict__ pos)
{
    int idx = blockIdx.x * blockDim.x + threadIdx.x;
    if (idx >= SEQ * 32) return;
    int s = idx >> 5;
    int p = idx & 31;
    float inv = powf(10000.0f, -(float)(2 * p) / (float)DH);
    float ang = (float)pos[s] * inv;
    float sv, cv;
    sincosf(ang, &sv, &cv);
    g_cos[idx] = cv;
    g_sin[idx] = sv;
}

// ---------------- converters ----------------
// 8 floats (2x float4) per thread for higher MLP / fewer blocks
__global__ void convert_x_kernel(const float* __restrict__ x)
{
    size_t i = ((size_t)blockIdx.x * blockDim.x + threadIdx.x) * 8;
    if (i >= (size_t)NROWS * DIM) return;
    float4 v0 = *(const float4*)(x + i);
    float4 v1 = *(const float4*)(x + i + 4);
    __half h0, l0, h1, l1, h2, l2, h3, l3;
    splitf(v0.x, h0, l0); splitf(v0.y, h1, l1);
    splitf(v0.z, h2, l2); splitf(v0.w, h3, l3);
    uint4 ph, pl;
    ph.x = pack2(h0, h1); ph.y = pack2(h2, h3);
    pl.x = pack2(l0, l1); pl.y = pack2(l2, l3);
    splitf(v1.x, h0, l0); splitf(v1.y, h1, l1);
    splitf(v1.z, h2, l2); splitf(v1.w, h3, l3);
    ph.z = pack2(h0, h1); ph.w = pack2(h2, h3);
    pl.z = pack2(l0, l1); pl.w = pack2(l2, l3);
    *(uint4*)&g_Xh[i] = ph;
    *(uint4*)&g_Xl[i] = pl;
}
__global__ void convert_w_all_kernel(const float* __restrict__ W0,
                                     const float* __restrict__ W1,
                                     const float* __restrict__ W2,
                                     const float* __restrict__ W3)
{
    int widx = blockIdx.y;
    const float* W = (widx == 0) ? W0 : (widx == 1) ? W1 : (widx == 2) ? W2 : W3;
    size_t i = ((size_t)blockIdx.x * blockDim.x + threadIdx.x) * 8;
    if (i >= (size_t)DIM * DIM) return;
    size_t o = (size_t)widx * DIM * DIM + i;
    float4 v0 = *(const float4*)(W + i);
    float4 v1 = *(const float4*)(W + i + 4);
    v0.x *= 256.0f; v0.y *= 256.0f; v0.z *= 256.0f; v0.w *= 256.0f;
    v1.x *= 256.0f; v1.y *= 256.0f; v1.z *= 256.0f; v1.w *= 256.0f;
    __half h0, l0, h1, l1, h2, l2, h3, l3;
    splitf(v0.x, h0, l0); splitf(v0.y, h1, l1);
    splitf(v0.z, h2, l2); splitf(v0.w, h3, l3);
    uint4 ph, pl;
    ph.x = pack2(h0, h1); ph.y = pack2(h2, h3);
    pl.x = pack2(l0, l1); pl.y = pack2(l2, l3);
    splitf(v1.x, h0, l0); splitf(v1.y, h1, l1);
    splitf(v1.z, h2, l2); splitf(v1.w, h3, l3);
    ph.z = pack2(h0, h1); ph.w = pack2(h2, h3);
    pl.z = pack2(l0, l1); pl.w = pack2(l2, l3);
    *(uint4*)&g_Wh[o] = ph;
    *(uint4*)&g_Wl[o] = pl;
}

// ---------------- fp16x2 GEMM: 4 warps x (64x64), 2-stage K32 (R10 exact) ----------------
#define GKP 40
#define GPL (128 * GKP)
#define GSTG (4 * GPL)
#define GEMM_SMEM (2 * GSTG * 2)  // 81920 B

template<bool FUSED>
__global__ void __launch_bounds__(128, 2) gemm_h2(float* __restrict__ Cout)
{
    extern __shared__ __half smh[];
    const int mode = FUSED ? (int)blockIdx.z : 3;
    const __half* Aph = FUSED ? g_Xh : g_Oh;
    const __half* Apl = FUSED ? g_Xl : g_Ol;
    const __half* Bph = g_Wh + (size_t)mode * DIM * DIM;
    const __half* Bpl = g_Wl + (size_t)mode * DIM * DIM;
    const uint32_t sb = (uint32_t)__cvta_generic_to_shared(smh);

    const int tid  = threadIdx.x;
    const int lane = tid & 31;
    const int wid  = tid >> 5;
    const int g    = lane >> 2;
    const int t    = lane & 3;
    const int wm   = wid & 1;
    const int wn   = wid >> 1;

    const int row0 = blockIdx.y * 128;
    const int col0 = blockIdx.x * 128;

    const int a_r = ((lane >> 3) & 1) * 8 + (lane & 7);
    const int a_c = ((lane >> 4) & 1) * 8;
    const int b_rsel = (lane >> 4);
    const int b_r = (lane & 7);
    const int b_c = ((lane >> 3) & 1) * 8;

    float acc[4][8][4];
    #pragma unroll
    for (int im = 0; im < 4; im++)
        #pragma unroll
        for (int in = 0; in < 8; in++)
            #pragma unroll
            for (int e = 0; e < 4; e++)
                acc[im][in][e] = 0.0f;

    auto load_stage = [&](int st, int kt) {
        const int k0 = kt * 32;
        #pragma unroll
        for (int i = 0; i < 16; i++) {
            int uidx = tid + i * 128;
            int p    = uidx >> 9;
            int w    = uidx & 511;
            int row  = w >> 2;
            int un   = (w & 3) * 8;
            const __half* src;
            if (p == 0)      src = Aph + (size_t)(row0 + row) * DIM + k0 + un;
            else if (p == 1) src = Apl + (size_t)(row0 + row) * DIM + k0 + un;
            else if (p == 2) src = Bph + (size_t)(col0 + row) * DIM + k0 + un;
            else             src = Bpl + (size_t)(col0 + row) * DIM + k0 + un;
            cp16h(&smh[st * GSTG + p * GPL + row * GKP + un], src);
        }
    };

    load_stage(0, 0);
    cp_commit();

    const int NKT = DIM / 32;
    for (int kt = 0; kt < NKT; kt++) {
        const int st = kt & 1;
        cp_wait<0>();
        __syncthreads();
        if (kt + 1 < NKT) { load_stage(st ^ 1, kt + 1); cp_commit(); }

        const uint32_t s0 = sb + (uint32_t)(st * GSTG) * 2u;
        #pragma unroll
        for (int kq = 0; kq < 2; kq++) {
            const int kk = kq * 16;
            uint32_t bh[8][2], bl[8][2];
            #pragma unroll
            for (int q = 0; q < 4; q++) {
                uint32_t boff = (uint32_t)((wn * 64 + (2 * q + b_rsel) * 8 + b_r) * GKP
                                           + kk + b_c) * 2u;
                ldmx4(bh[2*q][0], bh[2*q][1], bh[2*q+1][0], bh[2*q+1][1],
                      s0 + (uint32_t)(2 * GPL) * 2u + boff);
                ldmx4(bl[2*q][0], bl[2*q][1], bl[2*q+1][0], bl[2*q+1][1],
                      s0 + (uint32_t)(3 * GPL) * 2u + boff);
            }
            #pragma unroll
            for (int im = 0; im < 4; im++) {
                uint32_t aoff = (uint32_t)((wm * 64 + im * 16 + a_r) * GKP + kk + a_c) * 2u;
                uint32_t ahi[4], alo[4];
                ldmx4(ahi[0], ahi[1], ahi[2], ahi[3], s0 + aoff);
                ldmx4(alo[0], alo[1], alo[2], alo[3], s0 + (uint32_t)GPL * 2u + aoff);
                #pragma unroll
                for (int in = 0; in < 8; in++) {
                    mma16(acc[im][in], ahi, bh[in]);
                    mma16(acc[im][in], ahi, bl[in]);
                    mma16(acc[im][in], alo, bh[in]);
                }
            }
        }
        __syncthreads();
    }

    const float sc = 1.0f / 256.0f;
    #pragma unroll
    for (int im = 0; im < 4; im++) {
        int r0 = row0 + wm * 64 + im * 16 + g;
        int r1 = r0 + 8;
        #pragma unroll
        for (int in = 0; in < 8; in++) {
            int c = col0 + wn * 64 + in * 8 + 2 * t;
            float v0 = acc[im][in][0] * sc, v1 = acc[im][in][1] * sc;
            float v2 = acc[im][in][2] * sc, v3 = acc[im][in][3] * sc;
            if (!FUSED) {
                float2 o0 = { v0, v1 };
                float2 o1 = { v2, v3 };
                *(float2*)(Cout + (size_t)r0 * DIM + c) = o0;
                *(float2*)(Cout + (size_t)r1 * DIM + c) = o1;
            } else {
                if (mode <= 1) {
                    int p = (c & 63) >> 1;
                    int s0i = r0 & (SEQ - 1);
                    int s1i = r1 & (SEQ - 1);
                    float cv0 = g_cos[s0i * 32 + p], sv0 = g_sin[s0i * 32 + p];
                    float cv1 = g_cos[s1i * 32 + p], sv1 = g_sin[s1i * 32 + p];
                    float n0 = v0 * cv0 - v1 * sv0, n1 = v0 * sv0 + v1 * cv0;
                    float n2 = v2 * cv1 - v3 * sv1, n3 = v2 * sv1 + v3 * cv1;
                    v0 = n0; v1 = n1; v2 = n2; v3 = n3;
                }
                __half* Ch = (mode == 0) ? g_Qh : (mode == 1) ? g_Kh : g_Vh;
                __half* Cl = (mode == 0) ? g_Ql : (mode == 1) ? g_Kl : g_Vl;
                __half h0, l0, h1, l1;
                splitf(v0, h0, l0); splitf(v1, h1, l1);
                *(__half2*)&Ch[(size_t)r0 * DIM + c] = __halves2half2(h0, h1);
                *(__half2*)&Cl[(size_t)r0 * DIM + c] = __halves2half2(l0, l1);
                splitf(v2, h0, l0); splitf(v3, h1, l1);
                *(__half2*)&Ch[(size_t)r1 * DIM + c] = __halves2half2(h0, h1);
                *(__half2*)&Cl[(size_t)r1 * DIM + c] = __halves2half2(l0, l1);
            }
        }
    }
}

// ---------------- flash attention: R10 structure + exp2 softmax ----------------
#define AKP 72
#define OQH 0
#define OQL (128 * AKP)
#define OKV0 (2 * 128 * AKP)
#define KVSTG (4 * 64 * AKP)
#define ATT_SMEM ((OKV0 + 2 * KVSTG) * 2)     // 110592 B
#define SCALE_LOG2E 0.1803368801111204f       // 0.125 * log2(e)

__global__ void __launch_bounds__(128, 2) attn_h2_kernel()
{
    extern __shared__ __half smh[];
    __half* qh = smh + OQH;  __half* ql = smh + OQL;
    const uint32_t sb = (uint32_t)__cvta_generic_to_shared(smh);

    const int tid  = threadIdx.x;
    const int lane = tid & 31;
    const int wid  = tid >> 5;
    const int g    = lane >> 2;
    const int t    = lane & 3;

    const int qt = (int)gridDim.x - 1 - (int)blockIdx.x;
    const int q0 = qt * 128;
    const int bh_ = blockIdx.y;
    const int b  = bh_ >> 4;
    const int h  = bh_ & 15;

    const size_t base = (size_t)b * SEQ * DIM + h * DH;
    const __half* Qhb = g_Qh + base;  const __half* Qlb = g_Ql + base;
    const __half* Khb = g_Kh + base;  const __half* Klb = g_Kl + base;
    const __half* Vhb = g_Vh + base;  const __half* Vlb = g_Vl + base;

    const int a_r = ((lane >> 3) & 1) * 8 + (lane & 7);
    const int a_c = ((lane >> 4) & 1) * 8;
    const int b_rsel = (lane >> 4);
    const int b_r = (lane & 7);
    const int b_c = ((lane >> 3) & 1) * 8;

    #pragma unroll
    for (int i = 0; i < 16; i++) {
        int pos = tid + i * 128;
        int pl_ = pos >> 10;
        int w   = pos & 1023;
        int row = w >> 3;
        int u   = (w & 7) * 8;
        const __half* src = (pl_ == 0) ? Qhb : Qlb;
        __half* dst = (pl_ == 0) ? qh : ql;
        *(uint4*)&dst[row * AKP + u] = *(const uint4*)(src + (size_t)(q0 + row) * DIM + u);
    }

    auto load_kv = [&](int st, int kvt) {
        const int kv0 = kvt * 64;
        __half* kvbase = smh + OKV0 + st * KVSTG;
        #pragma unroll
        for (int i = 0; i < 16; i++) {
            int uidx = tid + i * 128;
            int p    = uidx >> 9;
            int w    = uidx & 511;
            int row  = w >> 3;
            int u    = (w & 7) * 8;
            const __half* src;
            if (p == 0)      src = Khb;
            else if (p == 1) src = Klb;
            else if (p == 2) src = Vhb;
            else             src = Vlb;
            cp16h(&kvbase[p * 64 * AKP + row * AKP + u],
                  src + (size_t)(kv0 + row) * DIM + u);
        }
    };

    float o[2][8][4];
    float m[4], l[4];
    #pragma unroll
    for (int im = 0; im < 2; im++)
        #pragma unroll
        for (int n = 0; n < 8; n++)
            #pragma unroll
            for (int e = 0; e < 4; e++)
                o[im][n][e] = 0.0f;
    #pragma unroll
    for (int i = 0; i < 4; i++) { m[i] = -INFINITY; l[i] = 0.0f; }

    const int rb  = wid * 32;
    const int wq0 = q0 + rb;
    const int ntiles = 2 * qt + 2;

    load_kv(0, 0);
    cp_commit();
    __syncthreads();

    for (int kvt = 0; kvt < ntiles; kvt++) {
        const int st = kvt & 1;
        const int kv0 = kvt * 64;
        cp_wait<0>();
        __syncthreads();
        if (kvt + 1 < ntiles) { load_kv(st ^ 1, kvt + 1); cp_commit(); }

        const uint32_t kvb = sb + (uint32_t)(OKV0 + st * KVSTG) * 2u;
        const uint32_t khB = kvb;
        const uint32_t klB = kvb + (uint32_t)(64 * AKP) * 2u;
        const uint32_t vhB = kvb + (uint32_t)(2 * 64 * AKP) * 2u;
        const uint32_t vlB = kvb + (uint32_t)(3 * 64 * AKP) * 2u;

        const bool active = (kv0 <= wq0 + 31);
        if (active) {
            float s[2][8][4];
            #pragma unroll
            for (int im = 0; im < 2; im++)
                #pragma unroll
                for (int n = 0; n < 8; n++)
                    #pragma unroll
                    for (int e = 0; e < 4; e++)
                        s[im][n][e] = 0.0f;

            #pragma unroll
            for (int ks = 0; ks < 4; ks++) {
                const int kk = ks * 16;
                uint32_t ahi[2][4], alo[2][4];
                #pragma unroll
                for (int im = 0; im < 2; im++) {
                    uint32_t aoff = (uint32_t)((rb + im * 16 + a_r) * AKP + kk + a_c) * 2u;
                    ldmx4(ahi[im][0], ahi[im][1], ahi[im][2], ahi[im][3],
                          sb + (uint32_t)(OQH * 2) + aoff);
                    ldmx4(alo[im][0], alo[im][1], alo[im][2], alo[im][3],
                          sb + (uint32_t)(OQL * 2) + aoff);
                }
                uint32_t bh[8][2], bl[8][2];
                #pragma unroll
                for (int q = 0; q < 4; q++) {
                    uint32_t boff = (uint32_t)(((2 * q + b_rsel) * 8 + b_r) * AKP
                                               + kk + b_c) * 2u;
                    ldmx4(bh[2*q][0], bh[2*q][1], bh[2*q+1][0], bh[2*q+1][1], khB + boff);
                    ldmx4(bl[2*q][0], bl[2*q][1], bl[2*q+1][0], bl[2*q+1][1], klB + boff);
                }
                #pragma unroll
                for (int im = 0; im < 2; im++)
                    #pragma unroll
                    for (int n = 0; n < 8; n++) {
                        mma16(s[im][n], ahi[im], bh[n]);
                        mma16(s[im][n], ahi[im], bl[n]);
                        mma16(s[im][n], alo[im], bh[n]);
                    }
            }

            const bool needmask = (kv0 + 63) > wq0;
            #pragma unroll
            for (int im = 0; im < 2; im++)
                #pragma unroll
                for (int n = 0; n < 8; n++)
                    #pragma unroll
                    for (int e = 0; e < 4; e++) {
                        float v = s[im][n][e] * SCALE_LOG2E;
                        if (needmask) {
                            int col = kv0 + n * 8 + 2 * t + (e & 1);
                            int row = wq0 + im * 16 + g + ((e >> 1) * 8);
                            if (col > row) v = -1e30f;
                        }
                        s[im][n][e] = v;
                    }

            #pragma unroll
            for (int im = 0; im < 2; im++) {
                #pragma unroll
                for (int hh = 0; hh < 2; hh++) {
                    int ri = im * 2 + hh;
                    float rowmax = -INFINITY;
                    #pragma unroll
                    for (int n = 0; n < 8; n++) {
                        rowmax = fmaxf(rowmax, s[im][n][hh * 2 + 0]);
                        rowmax = fmaxf(rowmax, s[im][n][hh * 2 + 1]);
                    }
                    rowmax = fmaxf(rowmax, __shfl_xor_sync(0xffffffffu, rowmax, 1));
                    rowmax = fmaxf(rowmax, __shfl_xor_sync(0xffffffffu, rowmax, 2));
                    float mnew = fmaxf(m[ri], rowmax);
                    float alpha = exp2f(m[ri] - mnew);
                    m[ri] = mnew;
                    float rs = 0.0f;
                    #pragma unroll
                    for (int n = 0; n < 8; n++) {
                        float p0 = exp2f(s[im][n][hh * 2 + 0] - mnew);
                        float p1 = exp2f(s[im][n][hh * 2 + 1] - mnew);
                        s[im][n][hh * 2 + 0] = p0;
                        s[im][n][hh * 2 + 1] = p1;
                        rs += p0 + p1;
                    }
                    rs += __shfl_xor_sync(0xffffffffu, rs, 1);
                    rs += __shfl_xor_sync(0xffffffffu, rs, 2);
                    l[ri] = l[ri] * alpha + rs;
                    #pragma unroll
                    for (int n = 0; n < 8; n++) {
                        o[im][n][hh * 2 + 0] *= alpha;
                        o[im][n][hh * 2 + 1] *= alpha;
                    }
                }
            }

            const int rml = ((lane >> 3) & 1) * 8 + (lane & 7);
            const int cml0 = (lane >> 4) * 8;
            #pragma unroll
            for (int ks = 0; ks < 4; ks++) {
                const int kk = ks * 16;
                uint32_t ahi[2][4], alo[2][4];
                #pragma unroll
                for (int im = 0; im < 2; im++) {
                    __half h0, l0_, h1, l1_;
                    splitf(s[im][2*ks][0] * 256.0f, h0, l0_);
                    splitf(s[im][2*ks][1] * 256.0f, h1, l1_);
                    ahi[im][0] = pack2(h0, h1);  alo[im][0] = pack2(l0_, l1_);
                    splitf(s[im][2*ks][2] * 256.0f, h0, l0_);
                    splitf(s[im][2*ks][3] * 256.0f, h1, l1_);
                    ahi[im][1] = pack2(h0, h1);  alo[im][1] = pack2(l0_, l1_);
                    splitf(s[im][2*ks+1][0] * 256.0f, h0, l0_);
                    splitf(s[im][2*ks+1][1] * 256.0f, h1, l1_);
                    ahi[im][2] = pack2(h0, h1);  alo[im][2] = pack2(l0_, l1_);
                    splitf(s[im][2*ks+1][2] * 256.0f, h0, l0_);
                    splitf(s[im][2*ks+1][3] * 256.0f, h1, l1_);
                    ahi[im][3] = pack2(h0, h1);  alo[im][3] = pack2(l0_, l1_);
                }
                #pragma unroll
                for (int nb = 0; nb < 4; nb++) {
                    uint32_t voff = (uint32_t)((kk + rml) * AKP + nb * 16 + cml0) * 2u;
                    uint32_t h0, h1, h2, h3, l0_, l1_, l2_, l3_;
                    ldmx4t(h0, h1, h2, h3, vhB + voff);
                    ldmx4t(l0_, l1_, l2_, l3_, vlB + voff);
                    uint32_t bh0[2] = { h0, h1 }, bh1[2] = { h2, h3 };
                    uint32_t bl0[2] = { l0_, l1_ }, bl1[2] = { l2_, l3_ };
                    #pragma unroll
                    for (int im = 0; im < 2; im++) {
                        mma16(o[im][2 * nb + 0], ahi[im], bh0);
                        mma16(o[im][2 * nb + 0], ahi[im], bl0);
                        mma16(o[im][2 * nb + 0], alo[im], bh0);
                        mma16(o[im][2 * nb + 1], ahi[im], bh1);
                        mma16(o[im][2 * nb + 1], ahi[im], bl1);
                        mma16(o[im][2 * nb + 1], alo[im], bh1);
                    }
                }
            }
        }
        __syncthreads();
    }

    __half* Ohb = g_Oh + base;
    __half* Olb = g_Ol + base;
    #pragma unroll
    for (int im = 0; im < 2; im++) {
        int r0 = q0 + rb + im * 16 + g;
        int r1 = r0 + 8;
        float inv0 = 1.0f / (256.0f * l[im * 2 + 0]);
        float inv1 = 1.0f / (256.0f * l[im * 2 + 1]);
        #pragma unroll
        for (int n = 0; n < 8; n++) {
            int c = n * 8 + 2 * t;
            __half h0, l0_, h1, l1_;
            splitf(o[im][n][0] * inv0, h0, l0_);
            splitf(o[im][n][1] * inv0, h1, l1_);
            *(__half2*)&Ohb[(size_t)r0 * DIM + c] = __halves2half2(h0, h1);
            *(__half2*)&Olb[(size_t)r0 * DIM + c] = __halves2half2(l0_, l1_);
            splitf(o[im][n][2] * inv1, h0, l0_);
            splitf(o[im][n][3] * inv1, h1, l1_);
            *(__half2*)&Ohb[(size_t)r1 * DIM + c] = __halves2half2(h0, h1);
            *(__half2*)&Olb[(size_t)r1 * DIM + c] = __halves2half2(l0_, l1_);
        }
    }
}

// ---------------- launch ----------------
extern "C" void kernel_launch(void* const* d_in, const int* in_sizes, int n_in,
                              void* d_out, int out_size)
{
    const float* x  = (const float*)d_in[0];
    const float* WQ = (const float*)d_in[1];
    const float* WK = (const float*)d_in[2];
    const float* WV = (const float*)d_in[3];
    const float* WO = (const float*)d_in[4];
    const int*  pos = (const int*)d_in[5];
    float* out = (float*)d_out;

    cudaFuncSetAttribute(gemm_h2<true>,  cudaFuncAttributeMaxDynamicSharedMemorySize, GEMM_SMEM);
    cudaFuncSetAttribute(gemm_h2<false>, cudaFuncAttributeMaxDynamicSharedMemorySize, GEMM_SMEM);
    cudaFuncSetAttribute(attn_h2_kernel, cudaFuncAttributeMaxDynamicSharedMemorySize, ATT_SMEM);

    rope_table_kernel<<<(SEQ * 32 + 255) / 256, 256>>>(pos);
    convert_x_kernel<<<(NROWS * DIM / 8 + 255) / 256, 256>>>(x);
    convert_w_all_kernel<<<dim3((DIM * DIM / 8 + 255) / 256, 4), 256>>>(WQ, WK, WV, WO);

    gemm_h2<true><<<dim3(DIM / 128, NROWS / 128, 3), 128, GEMM_SMEM>>>(nullptr);

    attn_h2_kernel<<<dim3(SEQ / 128, BATCH * NHEAD), 128, ATT_SMEM>>>();

    gemm_h2<false><<<dim3(DIM / 128, NROWS / 128, 1), 128, GEMM_SMEM>>>(out);
}

// round 16
// speedup vs baseline: 1.0854x; 1.0162x over previous
#include <cuda_runtime.h>
#include <cuda_fp16.h>
#include <math.h>
#include <stdint.h>

#define BATCH 4
#define SEQ   2048
#define DIM   1024
#define NHEAD 16
#define DH    64
#define NROWS (BATCH*SEQ)   // 8192

// ---------------- scratch (device globals) ----------------
__device__ __half g_Xh[(size_t)NROWS * DIM];
__device__ __half g_Xl[(size_t)NROWS * DIM];
__device__ __half g_Wh[(size_t)4 * DIM * DIM];
__device__ __half g_Wl[(size_t)4 * DIM * DIM];
__device__ __half g_Qh[(size_t)NROWS * DIM];
__device__ __half g_Ql[(size_t)NROWS * DIM];
__device__ __half g_Kh[(size_t)NROWS * DIM];
__device__ __half g_Kl[(size_t)NROWS * DIM];
__device__ __half g_Vh[(size_t)NROWS * DIM];
__device__ __half g_Vl[(size_t)NROWS * DIM];
__device__ __half g_Oh[(size_t)NROWS * DIM];
__device__ __half g_Ol[(size_t)NROWS * DIM];
__device__ float g_cos[SEQ * 32];
__device__ float g_sin[SEQ * 32];

// ---------------- helpers ----------------
__device__ __forceinline__ void splitf(float x, __half& h, __half& l) {
    h = __float2half_rn(x);
    l = __float2half_rn(x - __half2float(h));
}
__device__ __forceinline__ uint32_t pack2(__half a, __half b) {
    __half2 hh = __halves2half2(a, b);
    return *(uint32_t*)&hh;
}
__device__ __forceinline__ void mma16(float* c, const uint32_t* a, const uint32_t* b) {
    asm volatile(
        "mma.sync.aligned.m16n8k16.row.col.f32.f16.f16.f32 "
        "{%0,%1,%2,%3},{%4,%5,%6,%7},{%8,%9},{%0,%1,%2,%3};"
        : "+f"(c[0]), "+f"(c[1]), "+f"(c[2]), "+f"(c[3])
        : "r"(a[0]), "r"(a[1]), "r"(a[2]), "r"(a[3]), "r"(b[0]), "r"(b[1]));
}
__device__ __forceinline__ void ldmx4(uint32_t& d0, uint32_t& d1, uint32_t& d2, uint32_t& d3,
                                      uint32_t saddr) {
    asm volatile("ldmatrix.sync.aligned.m8n8.x4.shared.b16 {%0,%1,%2,%3}, [%4];"
                 : "=r"(d0), "=r"(d1), "=r"(d2), "=r"(d3) : "r"(saddr));
}
__device__ __forceinline__ void ldmx4t(uint32_t& d0, uint32_t& d1, uint32_t& d2, uint32_t& d3,
                                       uint32_t saddr) {
    asm volatile("ldmatrix.sync.aligned.m8n8.x4.trans.shared.b16 {%0,%1,%2,%3}, [%4];"
                 : "=r"(d0), "=r"(d1), "=r"(d2), "=r"(d3) : "r"(saddr));
}
__device__ __forceinline__ void cp16h(__half* dst, const __half* src) {
    unsigned s = (unsigned)__cvta_generic_to_shared(dst);
    asm volatile("cp.async.cg.shared.global [%0], [%1], 16;" :: "r"(s), "l"(src));
}
__device__ __forceinline__ void cp_commit() { asm volatile("cp.async.commit_group;"); }
template<int N>
__device__ __forceinline__ void cp_wait() { asm volatile("cp.async.wait_group %0;" :: "n"(N)); }

// ---------------- RoPE table ----------------
__global__ void rope_table_kernel(const int* __restrict__ pos)
{
    int idx = blockIdx.x * blockDim.x + threadIdx.x;
    if (idx >= SEQ * 32) return;
    int s = idx >> 5;
    int p = idx & 31;
    float inv = powf(10000.0f, -(float)(2 * p) / (float)DH);
    float ang = (float)pos[s] * inv;
    float sv, cv;
    sincosf(ang, &sv, &cv);
    g_cos[idx] = cv;
    g_sin[idx] = sv;
}

// ---------------- converters (8 floats/thread) ----------------
__global__ void convert_x_kernel(const float* __restrict__ x)
{
    size_t i = ((size_t)blockIdx.x * blockDim.x + threadIdx.x) * 8;
    if (i >= (size_t)NROWS * DIM) return;
    float4 v0 = *(const float4*)(x + i);
    float4 v1 = *(const float4*)(x + i + 4);
    __half h0, l0, h1, l1, h2, l2, h3, l3;
    splitf(v0.x, h0, l0); splitf(v0.y, h1, l1);
    splitf(v0.z, h2, l2); splitf(v0.w, h3, l3);
    uint4 ph, pl;
    ph.x = pack2(h0, h1); ph.y = pack2(h2, h3);
    pl.x = pack2(l0, l1); pl.y = pack2(l2, l3);
    splitf(v1.x, h0, l0); splitf(v1.y, h1, l1);
    splitf(v1.z, h2, l2); splitf(v1.w, h3, l3);
    ph.z = pack2(h0, h1); ph.w = pack2(h2, h3);
    pl.z = pack2(l0, l1); pl.w = pack2(l2, l3);
    *(uint4*)&g_Xh[i] = ph;
    *(uint4*)&g_Xl[i] = pl;
}
__global__ void convert_w_all_kernel(const float* __restrict__ W0,
                                     const float* __restrict__ W1,
                                     const float* __restrict__ W2,
                                     const float* __restrict__ W3)
{
    int widx = blockIdx.y;
    const float* W = (widx == 0) ? W0 : (widx == 1) ? W1 : (widx == 2) ? W2 : W3;
    size_t i = ((size_t)blockIdx.x * blockDim.x + threadIdx.x) * 8;
    if (i >= (size_t)DIM * DIM) return;
    size_t o = (size_t)widx * DIM * DIM + i;
    float4 v0 = *(const float4*)(W + i);
    float4 v1 = *(const float4*)(W + i + 4);
    v0.x *= 256.0f; v0.y *= 256.0f; v0.z *= 256.0f; v0.w *= 256.0f;
    v1.x *= 256.0f; v1.y *= 256.0f; v1.z *= 256.0f; v1.w *= 256.0f;
    __half h0, l0, h1, l1, h2, l2, h3, l3;
    splitf(v0.x, h0, l0); splitf(v0.y, h1, l1);
    splitf(v0.z, h2, l2); splitf(v0.w, h3, l3);
    uint4 ph, pl;
    ph.x = pack2(h0, h1); ph.y = pack2(h2, h3);
    pl.x = pack2(l0, l1); pl.y = pack2(l2, l3);
    splitf(v1.x, h0, l0); splitf(v1.y, h1, l1);
    splitf(v1.z, h2, l2); splitf(v1.w, h3, l3);
    ph.z = pack2(h0, h1); ph.w = pack2(h2, h3);
    pl.z = pack2(l0, l1); pl.w = pack2(l2, l3);
    *(uint4*)&g_Wh[o] = ph;
    *(uint4*)&g_Wl[o] = pl;
}

// ---------------- fp16x2 GEMM: R13 order (wait->sync->load), no trailing barrier ----------------
#define GKP 40
#define GPL (128 * GKP)
#define GSTG (4 * GPL)
#define GEMM_SMEM (2 * GSTG * 2)  // 81920 B

template<bool FUSED>
__global__ void __launch_bounds__(128, 2) gemm_h2(float* __restrict__ Cout)
{
    extern __shared__ __half smh[];
    const int mode = FUSED ? (int)blockIdx.z : 3;
    const __half* Aph = FUSED ? g_Xh : g_Oh;
    const __half* Apl = FUSED ? g_Xl : g_Ol;
    const __half* Bph = g_Wh + (size_t)mode * DIM * DIM;
    const __half* Bpl = g_Wl + (size_t)mode * DIM * DIM;
    const uint32_t sb = (uint32_t)__cvta_generic_to_shared(smh);

    const int tid  = threadIdx.x;
    const int lane = tid & 31;
    const int wid  = tid >> 5;
    const int g    = lane >> 2;
    const int t    = lane & 3;
    const int wm   = wid & 1;
    const int wn   = wid >> 1;

    const int row0 = blockIdx.y * 128;
    const int col0 = blockIdx.x * 128;

    const int a_r = ((lane >> 3) & 1) * 8 + (lane & 7);
    const int a_c = ((lane >> 4) & 1) * 8;
    const int b_rsel = (lane >> 4);
    const int b_r = (lane & 7);
    const int b_c = ((lane >> 3) & 1) * 8;

    float acc[4][8][4];
    #pragma unroll
    for (int im = 0; im < 4; im++)
        #pragma unroll
        for (int in = 0; in < 8; in++)
            #pragma unroll
            for (int e = 0; e < 4; e++)
                acc[im][in][e] = 0.0f;

    auto load_stage = [&](int st, int kt) {
        const int k0 = kt * 32;
        #pragma unroll
        for (int i = 0; i < 16; i++) {
            int uidx = tid + i * 128;
            int p    = uidx >> 9;
            int w    = uidx & 511;
            int row  = w >> 2;
            int un   = (w & 3) * 8;
            const __half* src;
            if (p == 0)      src = Aph + (size_t)(row0 + row) * DIM + k0 + un;
            else if (p == 1) src = Apl + (size_t)(row0 + row) * DIM + k0 + un;
            else if (p == 2) src = Bph + (size_t)(col0 + row) * DIM + k0 + un;
            else             src = Bpl + (size_t)(col0 + row) * DIM + k0 + un;
            cp16h(&smh[st * GSTG + p * GPL + row * GKP + un], src);
        }
    };

    load_stage(0, 0);
    cp_commit();

    const int NKT = DIM / 32;
    for (int kt = 0; kt < NKT; kt++) {
        const int st = kt & 1;
        cp_wait<0>();      // my stage-kt copies done
        __syncthreads();   // everyone's copies visible; everyone finished compute(kt-1)
        if (kt + 1 < NKT) { load_stage(st ^ 1, kt + 1); cp_commit(); }

        const uint32_t s0 = sb + (uint32_t)(st * GSTG) * 2u;
        #pragma unroll
        for (int kq = 0; kq < 2; kq++) {
            const int kk = kq * 16;
            uint32_t bh[8][2], bl[8][2];
            #pragma unroll
            for (int q = 0; q < 4; q++) {
                uint32_t boff = (uint32_t)((wn * 64 + (2 * q + b_rsel) * 8 + b_r) * GKP
                                           + kk + b_c) * 2u;
                ldmx4(bh[2*q][0], bh[2*q][1], bh[2*q+1][0], bh[2*q+1][1],
                      s0 + (uint32_t)(2 * GPL) * 2u + boff);
                ldmx4(bl[2*q][0], bl[2*q][1], bl[2*q+1][0], bl[2*q+1][1],
                      s0 + (uint32_t)(3 * GPL) * 2u + boff);
            }
            #pragma unroll
            for (int im = 0; im < 4; im++) {
                uint32_t aoff = (uint32_t)((wm * 64 + im * 16 + a_r) * GKP + kk + a_c) * 2u;
                uint32_t ahi[4], alo[4];
                ldmx4(ahi[0], ahi[1], ahi[2], ahi[3], s0 + aoff);
                ldmx4(alo[0], alo[1], alo[2], alo[3], s0 + (uint32_t)GPL * 2u + aoff);
                #pragma unroll
                for (int in = 0; in < 8; in++) {
                    mma16(acc[im][in], ahi, bh[in]);
                    mma16(acc[im][in], ahi, bl[in]);
                    mma16(acc[im][in], alo, bh[in]);
                }
            }
        }
        // no trailing barrier: the collective barrier at the top of iteration kt+1
        // orders this compute (reads of stage st) before any write to stage st at kt+2.
    }

    const float sc = 1.0f / 256.0f;
    #pragma unroll
    for (int im = 0; im < 4; im++) {
        int r0 = row0 + wm * 64 + im * 16 + g;
        int r1 = r0 + 8;
        #pragma unroll
        for (int in = 0; in < 8; in++) {
            int c = col0 + wn * 64 + in * 8 + 2 * t;
            float v0 = acc[im][in][0] * sc, v1 = acc[im][in][1] * sc;
            float v2 = acc[im][in][2] * sc, v3 = acc[im][in][3] * sc;
            if (!FUSED) {
                float2 o0 = { v0, v1 };
                float2 o1 = { v2, v3 };
                *(float2*)(Cout + (size_t)r0 * DIM + c) = o0;
                *(float2*)(Cout + (size_t)r1 * DIM + c) = o1;
            } else {
                if (mode <= 1) {
                    int p = (c & 63) >> 1;
                    int s0i = r0 & (SEQ - 1);
                    int s1i = r1 & (SEQ - 1);
                    float cv0 = g_cos[s0i * 32 + p], sv0 = g_sin[s0i * 32 + p];
                    float cv1 = g_cos[s1i * 32 + p], sv1 = g_sin[s1i * 32 + p];
                    float n0 = v0 * cv0 - v1 * sv0, n1 = v0 * sv0 + v1 * cv0;
                    float n2 = v2 * cv1 - v3 * sv1, n3 = v2 * sv1 + v3 * cv1;
                    v0 = n0; v1 = n1; v2 = n2; v3 = n3;
                }
                __half* Ch = (mode == 0) ? g_Qh : (mode == 1) ? g_Kh : g_Vh;
                __half* Cl = (mode == 0) ? g_Ql : (mode == 1) ? g_Kl : g_Vl;
                __half h0, l0, h1, l1;
                splitf(v0, h0, l0); splitf(v1, h1, l1);
                *(__half2*)&Ch[(size_t)r0 * DIM + c] = __halves2half2(h0, h1);
                *(__half2*)&Cl[(size_t)r0 * DIM + c] = __halves2half2(l0, l1);
                splitf(v2, h0, l0); splitf(v3, h1, l1);
                *(__half2*)&Ch[(size_t)r1 * DIM + c] = __halves2half2(h0, h1);
                *(__half2*)&Cl[(size_t)r1 * DIM + c] = __halves2half2(l0, l1);
            }
        }
    }
}

// ---------------- flash attention: R13 order, no trailing barrier ----------------
#define AKP 72
#define OQH 0
#define OQL (128 * AKP)
#define OKV0 (2 * 128 * AKP)
#define KVSTG (4 * 64 * AKP)
#define ATT_SMEM ((OKV0 + 2 * KVSTG) * 2)     // 110592 B
#define SCALE_LOG2E 0.1803368801111204f       // 0.125 * log2(e)

__global__ void __launch_bounds__(128, 2) attn_h2_kernel()
{
    extern __shared__ __half smh[];
    __half* qh = smh + OQH;  __half* ql = smh + OQL;
    const uint32_t sb = (uint32_t)__cvta_generic_to_shared(smh);

    const int tid  = threadIdx.x;
    const int lane = tid & 31;
    const int wid  = tid >> 5;
    const int g    = lane >> 2;
    const int t    = lane & 3;

    const int qt = (int)gridDim.x - 1 - (int)blockIdx.x;
    const int q0 = qt * 128;
    const int bh_ = blockIdx.y;
    const int b  = bh_ >> 4;
    const int h  = bh_ & 15;

    const size_t base = (size_t)b * SEQ * DIM + h * DH;
    const __half* Qhb = g_Qh + base;  const __half* Qlb = g_Ql + base;
    const __half* Khb = g_Kh + base;  const __half* Klb = g_Kl + base;
    const __half* Vhb = g_Vh + base;  const __half* Vlb = g_Vl + base;

    const int a_r = ((lane >> 3) & 1) * 8 + (lane & 7);
    const int a_c = ((lane >> 4) & 1) * 8;
    const int b_rsel = (lane >> 4);
    const int b_r = (lane & 7);
    const int b_c = ((lane >> 3) & 1) * 8;

    #pragma unroll
    for (int i = 0; i < 16; i++) {
        int pos = tid + i * 128;
        int pl_ = pos >> 10;
        int w   = pos & 1023;
        int row = w >> 3;
        int u   = (w & 7) * 8;
        const __half* src = (pl_ == 0) ? Qhb : Qlb;
        __half* dst = (pl_ == 0) ? qh : ql;
        *(uint4*)&dst[row * AKP + u] = *(const uint4*)(src + (size_t)(q0 + row) * DIM + u);
    }

    auto load_kv = [&](int st, int kvt) {
        const int kv0 = kvt * 64;
        __half* kvbase = smh + OKV0 + st * KVSTG;
        #pragma unroll
        for (int i = 0; i < 16; i++) {
            int uidx = tid + i * 128;
            int p    = uidx >> 9;
            int w    = uidx & 511;
            int row  = w >> 3;
            int u    = (w & 7) * 8;
            const __half* src;
            if (p == 0)      src = Khb;
            else if (p == 1) src = Klb;
            else if (p == 2) src = Vhb;
            else             src = Vlb;
            cp16h(&kvbase[p * 64 * AKP + row * AKP + u],
                  src + (size_t)(kv0 + row) * DIM + u);
        }
    };

    float o[2][8][4];
    float m[4], l[4];
    #pragma unroll
    for (int im = 0; im < 2; im++)
        #pragma unroll
        for (int n = 0; n < 8; n++)
            #pragma unroll
            for (int e = 0; e < 4; e++)
                o[im][n][e] = 0.0f;
    #pragma unroll
    for (int i = 0; i < 4; i++) { m[i] = -INFINITY; l[i] = 0.0f; }

    const int rb  = wid * 32;
    const int wq0 = q0 + rb;
    const int ntiles = 2 * qt + 2;

    load_kv(0, 0);
    cp_commit();

    for (int kvt = 0; kvt < ntiles; kvt++) {
        const int st = kvt & 1;
        const int kv0 = kvt * 64;
        cp_wait<0>();
        __syncthreads();   // copies visible to all; stage st^1 free; Q visible (iter 0)
        if (kvt + 1 < ntiles) { load_kv(st ^ 1, kvt + 1); cp_commit(); }

        const uint32_t kvb = sb + (uint32_t)(OKV0 + st * KVSTG) * 2u;
        const uint32_t khB = kvb;
        const uint32_t klB = kvb + (uint32_t)(64 * AKP) * 2u;
        const uint32_t vhB = kvb + (uint32_t)(2 * 64 * AKP) * 2u;
        const uint32_t vlB = kvb + (uint32_t)(3 * 64 * AKP) * 2u;

        const bool active = (kv0 <= wq0 + 31);
        if (active) {
            float s[2][8][4];
            #pragma unroll
            for (int im = 0; im < 2; im++)
                #pragma unroll
                for (int n = 0; n < 8; n++)
                    #pragma unroll
                    for (int e = 0; e < 4; e++)
                        s[im][n][e] = 0.0f;

            #pragma unroll
            for (int ks = 0; ks < 4; ks++) {
                const int kk = ks * 16;
                uint32_t ahi[2][4], alo[2][4];
                #pragma unroll
                for (int im = 0; im < 2; im++) {
                    uint32_t aoff = (uint32_t)((rb + im * 16 + a_r) * AKP + kk + a_c) * 2u;
                    ldmx4(ahi[im][0], ahi[im][1], ahi[im][2], ahi[im][3],
                          sb + (uint32_t)(OQH * 2) + aoff);
                    ldmx4(alo[im][0], alo[im][1], alo[im][2], alo[im][3],
                          sb + (uint32_t)(OQL * 2) + aoff);
                }
                uint32_t bh[8][2], bl[8][2];
                #pragma unroll
                for (int q = 0; q < 4; q++) {
                    uint32_t boff = (uint32_t)(((2 * q + b_rsel) * 8 + b_r) * AKP
                                               + kk + b_c) * 2u;
                    ldmx4(bh[2*q][0], bh[2*q][1], bh[2*q+1][0], bh[2*q+1][1], khB + boff);
                    ldmx4(bl[2*q][0], bl[2*q][1], bl[2*q+1][0], bl[2*q+1][1], klB + boff);
                }
                #pragma unroll
                for (int im = 0; im < 2; im++)
                    #pragma unroll
                    for (int n = 0; n < 8; n++) {
                        mma16(s[im][n], ahi[im], bh[n]);
                        mma16(s[im][n], ahi[im], bl[n]);
                        mma16(s[im][n], alo[im], bh[n]);
                    }
            }

            const bool needmask = (kv0 + 63) > wq0;
            #pragma unroll
            for (int im = 0; im < 2; im++)
                #pragma unroll
                for (int n = 0; n < 8; n++)
                    #pragma unroll
                    for (int e = 0; e < 4; e++) {
                        float v = s[im][n][e] * SCALE_LOG2E;
                        if (needmask) {
                            int col = kv0 + n * 8 + 2 * t + (e & 1);
                            int row = wq0 + im * 16 + g + ((e >> 1) * 8);
                            if (col > row) v = -1e30f;
                        }
                        s[im][n][e] = v;
                    }

            #pragma unroll
            for (int im = 0; im < 2; im++) {
                #pragma unroll
                for (int hh = 0; hh < 2; hh++) {
                    int ri = im * 2 + hh;
                    float rowmax = -INFINITY;
                    #pragma unroll
                    for (int n = 0; n < 8; n++) {
                        rowmax = fmaxf(rowmax, s[im][n][hh * 2 + 0]);
                        rowmax = fmaxf(rowmax, s[im][n][hh * 2 + 1]);
                    }
                    rowmax = fmaxf(rowmax, __shfl_xor_sync(0xffffffffu, rowmax, 1));
                    rowmax = fmaxf(rowmax, __shfl_xor_sync(0xffffffffu, rowmax, 2));
                    float mnew = fmaxf(m[ri], rowmax);
                    float alpha = exp2f(m[ri] - mnew);
                    m[ri] = mnew;
                    float rs = 0.0f;
                    #pragma unroll
                    for (int n = 0; n < 8; n++) {
                        float p0 = exp2f(s[im][n][hh * 2 + 0] - mnew);
                        float p1 = exp2f(s[im][n][hh * 2 + 1] - mnew);
                        s[im][n][hh * 2 + 0] = p0;
                        s[im][n][hh * 2 + 1] = p1;
                        rs += p0 + p1;
                    }
                    rs += __shfl_xor_sync(0xffffffffu, rs, 1);
                    rs += __shfl_xor_sync(0xffffffffu, rs, 2);
                    l[ri] = l[ri] * alpha + rs;
                    #pragma unroll
                    for (int n = 0; n < 8; n++) {
                        o[im][n][hh * 2 + 0] *= alpha;
                        o[im][n][hh * 2 + 1] *= alpha;
                    }
                }
            }

            const int rml = ((lane >> 3) & 1) * 8 + (lane & 7);
            const int cml0 = (lane >> 4) * 8;
            #pragma unroll
            for (int ks = 0; ks < 4; ks++) {
                const int kk = ks * 16;
                uint32_t ahi[2][4], alo[2][4];
                #pragma unroll
                for (int im = 0; im < 2; im++) {
                    __half h0, l0_, h1, l1_;
                    splitf(s[im][2*ks][0] * 256.0f, h0, l0_);
                    splitf(s[im][2*ks][1] * 256.0f, h1, l1_);
                    ahi[im][0] = pack2(h0, h1);  alo[im][0] = pack2(l0_, l1_);
                    splitf(s[im][2*ks][2] * 256.0f, h0, l0_);
                    splitf(s[im][2*ks][3] * 256.0f, h1, l1_);
                    ahi[im][1] = pack2(h0, h1);  alo[im][1] = pack2(l0_, l1_);
                    splitf(s[im][2*ks+1][0] * 256.0f, h0, l0_);
                    splitf(s[im][2*ks+1][1] * 256.0f, h1, l1_);
                    ahi[im][2] = pack2(h0, h1);  alo[im][2] = pack2(l0_, l1_);
                    splitf(s[im][2*ks+1][2] * 256.0f, h0, l0_);
                    splitf(s[im][2*ks+1][3] * 256.0f, h1, l1_);
                    ahi[im][3] = pack2(h0, h1);  alo[im][3] = pack2(l0_, l1_);
                }
                #pragma unroll
                for (int nb = 0; nb < 4; nb++) {
                    uint32_t voff = (uint32_t)((kk + rml) * AKP + nb * 16 + cml0) * 2u;
                    uint32_t h0, h1, h2, h3, l0_, l1_, l2_, l3_;
                    ldmx4t(h0, h1, h2, h3, vhB + voff);
                    ldmx4t(l0_, l1_, l2_, l3_, vlB + voff);
                    uint32_t bh0[2] = { h0, h1 }, bh1[2] = { h2, h3 };
                    uint32_t bl0[2] = { l0_, l1_ }, bl1[2] = { l2_, l3_ };
                    #pragma unroll
                    for (int im = 0; im < 2; im++) {
                        mma16(o[im][2 * nb + 0], ahi[im], bh0);
                        mma16(o[im][2 * nb + 0], ahi[im], bl0);
                        mma16(o[im][2 * nb + 0], alo[im], bh0);
                        mma16(o[im][2 * nb + 1], ahi[im], bh1);
                        mma16(o[im][2 * nb + 1], ahi[im], bl1);
                        mma16(o[im][2 * nb + 1], alo[im], bh1);
                    }
                }
            }
        }
        // no trailing barrier: next iteration's top (wait -> sync) provides all ordering
    }

    __half* Ohb = g_Oh + base;
    __half* Olb = g_Ol + base;
    #pragma unroll
    for (int im = 0; im < 2; im++) {
        int r0 = q0 + rb + im * 16 + g;
        int r1 = r0 + 8;
        float inv0 = 1.0f / (256.0f * l[im * 2 + 0]);
        float inv1 = 1.0f / (256.0f * l[im * 2 + 1]);
        #pragma unroll
        for (int n = 0; n < 8; n++) {
            int c = n * 8 + 2 * t;
            __half h0, l0_, h1, l1_;
            splitf(o[im][n][0] * inv0, h0, l0_);
            splitf(o[im][n][1] * inv0, h1, l1_);
            *(__half2*)&Ohb[(size_t)r0 * DIM + c] = __halves2half2(h0, h1);
            *(__half2*)&Olb[(size_t)r0 * DIM + c] = __halves2half2(l0_, l1_);
            splitf(o[im][n][2] * inv1, h0, l0_);
            splitf(o[im][n][3] * inv1, h1, l1_);
            *(__half2*)&Ohb[(size_t)r1 * DIM + c] = __halves2half2(h0, h1);
            *(__half2*)&Olb[(size_t)r1 * DIM + c] = __halves2half2(l0_, l1_);
        }
    }
}

// ---------------- launch ----------------
extern "C" void kernel_launch(void* const* d_in, const int* in_sizes, int n_in,
                              void* d_out, int out_size)
{
    const float* x  = (const float*)d_in[0];
    const float* WQ = (const float*)d_in[1];
    const float* WK = (const float*)d_in[2];
    const float* WV = (const float*)d_in[3];
    const float* WO = (const float*)d_in[4];
    const int*  pos = (const int*)d_in[5];
    float* out = (float*)d_out;

    cudaFuncSetAttribute(gemm_h2<true>,  cudaFuncAttributeMaxDynamicSharedMemorySize, GEMM_SMEM);
    cudaFuncSetAttribute(gemm_h2<false>, cudaFuncAttributeMaxDynamicSharedMemorySize, GEMM_SMEM);
    cudaFuncSetAttribute(attn_h2_kernel, cudaFuncAttributeMaxDynamicSharedMemorySize, ATT_SMEM);

    rope_table_kernel<<<(SEQ * 32 + 255) / 256, 256>>>(pos);
    convert_x_kernel<<<(NROWS * DIM / 8 + 255) / 256, 256>>>(x);
    convert_w_all_kernel<<<dim3((DIM * DIM / 8 + 255) / 256, 4), 256>>>(WQ, WK, WV, WO);

    gemm_h2<true><<<dim3(DIM / 128, NROWS / 128, 3), 128, GEMM_SMEM>>>(nullptr);

    attn_h2_kernel<<<dim3(SEQ / 128, BATCH * NHEAD), 128, ATT_SMEM>>>();

    gemm_h2<false><<<dim3(DIM / 128, NROWS / 128, 1), 128, GEMM_SMEM>>>(out);
}

// round 17
// speedup vs baseline: 1.1545x; 1.0637x over previous
#include <cuda_runtime.h>
#include <cuda_fp16.h>
#include <math.h>
#include <stdint.h>

#define BATCH 4
#define SEQ   2048
#define DIM   1024
#define NHEAD 16
#define DH    64
#define NROWS (BATCH*SEQ)   // 8192

// ---------------- scratch (device globals) ----------------
__device__ __half g_Xh[(size_t)NROWS * DIM];
__device__ __half g_Xl[(size_t)NROWS * DIM];
__device__ __half g_Wh[(size_t)4 * DIM * DIM];
__device__ __half g_Wl[(size_t)4 * DIM * DIM];
__device__ __half g_Qh[(size_t)NROWS * DIM];
__device__ __half g_Ql[(size_t)NROWS * DIM];
__device__ __half g_Kh[(size_t)NROWS * DIM];
__device__ __half g_Kl[(size_t)NROWS * DIM];
__device__ __half g_Vh[(size_t)NROWS * DIM];
__device__ __half g_Vl[(size_t)NROWS * DIM];
__device__ __half g_Oh[(size_t)NROWS * DIM];
__device__ __half g_Ol[(size_t)NROWS * DIM];
__device__ float g_cos[SEQ * 32];
__device__ float g_sin[SEQ * 32];

// ---------------- helpers ----------------
__device__ __forceinline__ void splitf(float x, __half& h, __half& l) {
    h = __float2half_rn(x);
    l = __float2half_rn(x - __half2float(h));
}
__device__ __forceinline__ uint32_t pack2(__half a, __half b) {
    __half2 hh = __halves2half2(a, b);
    return *(uint32_t*)&hh;
}
__device__ __forceinline__ void mma16(float* c, const uint32_t* a, const uint32_t* b) {
    asm volatile(
        "mma.sync.aligned.m16n8k16.row.col.f32.f16.f16.f32 "
        "{%0,%1,%2,%3},{%4,%5,%6,%7},{%8,%9},{%0,%1,%2,%3};"
        : "+f"(c[0]), "+f"(c[1]), "+f"(c[2]), "+f"(c[3])
        : "r"(a[0]), "r"(a[1]), "r"(a[2]), "r"(a[3]), "r"(b[0]), "r"(b[1]));
}
__device__ __forceinline__ void ldmx4(uint32_t& d0, uint32_t& d1, uint32_t& d2, uint32_t& d3,
                                      uint32_t saddr) {
    asm volatile("ldmatrix.sync.aligned.m8n8.x4.shared.b16 {%0,%1,%2,%3}, [%4];"
                 : "=r"(d0), "=r"(d1), "=r"(d2), "=r"(d3) : "r"(saddr));
}
__device__ __forceinline__ void ldmx4t(uint32_t& d0, uint32_t& d1, uint32_t& d2, uint32_t& d3,
                                       uint32_t saddr) {
    asm volatile("ldmatrix.sync.aligned.m8n8.x4.trans.shared.b16 {%0,%1,%2,%3}, [%4];"
                 : "=r"(d0), "=r"(d1), "=r"(d2), "=r"(d3) : "r"(saddr));
}
__device__ __forceinline__ void cp16h(__half* dst, const __half* src) {
    unsigned s = (unsigned)__cvta_generic_to_shared(dst);
    asm volatile("cp.async.cg.shared.global [%0], [%1], 16;" :: "r"(s), "l"(src));
}
__device__ __forceinline__ void cp_commit() { asm volatile("cp.async.commit_group;"); }
template<int N>
__device__ __forceinline__ void cp_wait() { asm volatile("cp.async.wait_group %0;" :: "n"(N)); }

// ---------------- RoPE table ----------------
__global__ void rope_table_kernel(const int* __restrict__ pos)
{
    int idx = blockIdx.x * blockDim.x + threadIdx.x;
    if (idx >= SEQ * 32) return;
    int s = idx >> 5;
    int p = idx & 31;
    float inv = powf(10000.0f, -(float)(2 * p) / (float)DH);
    float ang = (float)pos[s] * inv;
    float sv, cv;
    sincosf(ang, &sv, &cv);
    g_cos[idx] = cv;
    g_sin[idx] = sv;
}

// ---------------- converters (8 floats/thread) ----------------
__global__ void convert_x_kernel(const float* __restrict__ x)
{
    size_t i = ((size_t)blockIdx.x * blockDim.x + threadIdx.x) * 8;
    if (i >= (size_t)NROWS * DIM) return;
    float4 v0 = *(const float4*)(x + i);
    float4 v1 = *(const float4*)(x + i + 4);
    __half h0, l0, h1, l1, h2, l2, h3, l3;
    splitf(v0.x, h0, l0); splitf(v0.y, h1, l1);
    splitf(v0.z, h2, l2); splitf(v0.w, h3, l3);
    uint4 ph, pl;
    ph.x = pack2(h0, h1); ph.y = pack2(h2, h3);
    pl.x = pack2(l0, l1); pl.y = pack2(l2, l3);
    splitf(v1.x, h0, l0); splitf(v1.y, h1, l1);
    splitf(v1.z, h2, l2); splitf(v1.w, h3, l3);
    ph.z = pack2(h0, h1); ph.w = pack2(h2, h3);
    pl.z = pack2(l0, l1); pl.w = pack2(l2, l3);
    *(uint4*)&g_Xh[i] = ph;
    *(uint4*)&g_Xl[i] = pl;
}
__global__ void convert_w_all_kernel(const float* __restrict__ W0,
                                     const float* __restrict__ W1,
                                     const float* __restrict__ W2,
                                     const float* __restrict__ W3)
{
    int widx = blockIdx.y;
    const float* W = (widx == 0) ? W0 : (widx == 1) ? W1 : (widx == 2) ? W2 : W3;
    size_t i = ((size_t)blockIdx.x * blockDim.x + threadIdx.x) * 8;
    if (i >= (size_t)DIM * DIM) return;
    size_t o = (size_t)widx * DIM * DIM + i;
    float4 v0 = *(const float4*)(W + i);
    float4 v1 = *(const float4*)(W + i + 4);
    v0.x *= 256.0f; v0.y *= 256.0f; v0.z *= 256.0f; v0.w *= 256.0f;
    v1.x *= 256.0f; v1.y *= 256.0f; v1.z *= 256.0f; v1.w *= 256.0f;
    __half h0, l0, h1, l1, h2, l2, h3, l3;
    splitf(v0.x, h0, l0); splitf(v0.y, h1, l1);
    splitf(v0.z, h2, l2); splitf(v0.w, h3, l3);
    uint4 ph, pl;
    ph.x = pack2(h0, h1); ph.y = pack2(h2, h3);
    pl.x = pack2(l0, l1); pl.y = pack2(l2, l3);
    splitf(v1.x, h0, l0); splitf(v1.y, h1, l1);
    splitf(v1.z, h2, l2); splitf(v1.w, h3, l3);
    ph.z = pack2(h0, h1); ph.w = pack2(h2, h3);
    pl.z = pack2(l0, l1); pl.w = pack2(l2, l3);
    *(uint4*)&g_Wh[o] = ph;
    *(uint4*)&g_Wl[o] = pl;
}

// ---------------- fp16x2 GEMM: mid-chunk prefetch issue ----------------
#define GKP 40
#define GPL (128 * GKP)
#define GSTG (4 * GPL)
#define GEMM_SMEM (2 * GSTG * 2)  // 81920 B

template<bool FUSED>
__global__ void __launch_bounds__(128, 2) gemm_h2(float* __restrict__ Cout)
{
    extern __shared__ __half smh[];
    const int mode = FUSED ? (int)blockIdx.z : 3;
    const __half* Aph = FUSED ? g_Xh : g_Oh;
    const __half* Apl = FUSED ? g_Xl : g_Ol;
    const __half* Bph = g_Wh + (size_t)mode * DIM * DIM;
    const __half* Bpl = g_Wl + (size_t)mode * DIM * DIM;
    const uint32_t sb = (uint32_t)__cvta_generic_to_shared(smh);

    const int tid  = threadIdx.x;
    const int lane = tid & 31;
    const int wid  = tid >> 5;
    const int g    = lane >> 2;
    const int t    = lane & 3;
    const int wm   = wid & 1;
    const int wn   = wid >> 1;

    const int row0 = blockIdx.y * 128;
    const int col0 = blockIdx.x * 128;

    const int a_r = ((lane >> 3) & 1) * 8 + (lane & 7);
    const int a_c = ((lane >> 4) & 1) * 8;
    const int b_rsel = (lane >> 4);
    const int b_r = (lane & 7);
    const int b_c = ((lane >> 3) & 1) * 8;

    float acc[4][8][4];
    #pragma unroll
    for (int im = 0; im < 4; im++)
        #pragma unroll
        for (int in = 0; in < 8; in++)
            #pragma unroll
            for (int e = 0; e < 4; e++)
                acc[im][in][e] = 0.0f;

    auto load_stage = [&](int st, int kt) {
        const int k0 = kt * 32;
        #pragma unroll
        for (int i = 0; i < 16; i++) {
            int uidx = tid + i * 128;
            int p    = uidx >> 9;
            int w    = uidx & 511;
            int row  = w >> 2;
            int un   = (w & 3) * 8;
            const __half* src;
            if (p == 0)      src = Aph + (size_t)(row0 + row) * DIM + k0 + un;
            else if (p == 1) src = Apl + (size_t)(row0 + row) * DIM + k0 + un;
            else if (p == 2) src = Bph + (size_t)(col0 + row) * DIM + k0 + un;
            else             src = Bpl + (size_t)(col0 + row) * DIM + k0 + un;
            cp16h(&smh[st * GSTG + p * GPL + row * GKP + un], src);
        }
    };

    auto compute_half = [&](uint32_t s0, int kq) {
        const int kk = kq * 16;
        uint32_t bh[8][2], bl[8][2];
        #pragma unroll
        for (int q = 0; q < 4; q++) {
            uint32_t boff = (uint32_t)((wn * 64 + (2 * q + b_rsel) * 8 + b_r) * GKP
                                       + kk + b_c) * 2u;
            ldmx4(bh[2*q][0], bh[2*q][1], bh[2*q+1][0], bh[2*q+1][1],
                  s0 + (uint32_t)(2 * GPL) * 2u + boff);
            ldmx4(bl[2*q][0], bl[2*q][1], bl[2*q+1][0], bl[2*q+1][1],
                  s0 + (uint32_t)(3 * GPL) * 2u + boff);
        }
        #pragma unroll
        for (int im = 0; im < 4; im++) {
            uint32_t aoff = (uint32_t)((wm * 64 + im * 16 + a_r) * GKP + kk + a_c) * 2u;
            uint32_t ahi[4], alo[4];
            ldmx4(ahi[0], ahi[1], ahi[2], ahi[3], s0 + aoff);
            ldmx4(alo[0], alo[1], alo[2], alo[3], s0 + (uint32_t)GPL * 2u + aoff);
            #pragma unroll
            for (int in = 0; in < 8; in++) {
                mma16(acc[im][in], ahi, bh[in]);
                mma16(acc[im][in], ahi, bl[in]);
                mma16(acc[im][in], alo, bh[in]);
            }
        }
    };

    load_stage(0, 0);
    cp_commit();

    const int NKT = DIM / 32;
    for (int kt = 0; kt < NKT; kt++) {
        const int st = kt & 1;
        cp_wait<0>();      // my stage-kt copies done
        __syncthreads();   // everyone's copies visible; everyone finished compute(kt-1)

        const uint32_t s0 = sb + (uint32_t)(st * GSTG) * 2u;
        compute_half(s0, 0);
        // mid-chunk prefetch issue: off the post-barrier critical path,
        // still after this iteration's barrier (WAR on stage st^1 safe),
        // exactly one commit per iteration (group count uniform).
        if (kt + 1 < NKT) load_stage(st ^ 1, kt + 1);
        cp_commit();
        compute_half(s0, 1);
        // no trailing barrier: next iteration's (wait -> sync) provides ordering
    }

    const float sc = 1.0f / 256.0f;
    #pragma unroll
    for (int im = 0; im < 4; im++) {
        int r0 = row0 + wm * 64 + im * 16 + g;
        int r1 = r0 + 8;
        #pragma unroll
        for (int in = 0; in < 8; in++) {
            int c = col0 + wn * 64 + in * 8 + 2 * t;
            float v0 = acc[im][in][0] * sc, v1 = acc[im][in][1] * sc;
            float v2 = acc[im][in][2] * sc, v3 = acc[im][in][3] * sc;
            if (!FUSED) {
                float2 o0 = { v0, v1 };
                float2 o1 = { v2, v3 };
                *(float2*)(Cout + (size_t)r0 * DIM + c) = o0;
                *(float2*)(Cout + (size_t)r1 * DIM + c) = o1;
            } else {
                if (mode <= 1) {
                    int p = (c & 63) >> 1;
                    int s0i = r0 & (SEQ - 1);
                    int s1i = r1 & (SEQ - 1);
                    float cv0 = g_cos[s0i * 32 + p], sv0 = g_sin[s0i * 32 + p];
                    float cv1 = g_cos[s1i * 32 + p], sv1 = g_sin[s1i * 32 + p];
                    float n0 = v0 * cv0 - v1 * sv0, n1 = v0 * sv0 + v1 * cv0;
                    float n2 = v2 * cv1 - v3 * sv1, n3 = v2 * sv1 + v3 * cv1;
                    v0 = n0; v1 = n1; v2 = n2; v3 = n3;
                }
                __half* Ch = (mode == 0) ? g_Qh : (mode == 1) ? g_Kh : g_Vh;
                __half* Cl = (mode == 0) ? g_Ql : (mode == 1) ? g_Kl : g_Vl;
                __half h0, l0, h1, l1;
                splitf(v0, h0, l0); splitf(v1, h1, l1);
                *(__half2*)&Ch[(size_t)r0 * DIM + c] = __halves2half2(h0, h1);
                *(__half2*)&Cl[(size_t)r0 * DIM + c] = __halves2half2(l0, l1);
                splitf(v2, h0, l0); splitf(v3, h1, l1);
                *(__half2*)&Ch[(size_t)r1 * DIM + c] = __halves2half2(h0, h1);
                *(__half2*)&Cl[(size_t)r1 * DIM + c] = __halves2half2(l0, l1);
            }
        }
    }
}

// ---------------- flash attention: mid-tile prefetch issue ----------------
#define AKP 72
#define OQH 0
#define OQL (128 * AKP)
#define OKV0 (2 * 128 * AKP)
#define KVSTG (4 * 64 * AKP)
#define ATT_SMEM ((OKV0 + 2 * KVSTG) * 2)     // 110592 B
#define SCALE_LOG2E 0.1803368801111204f       // 0.125 * log2(e)

__global__ void __launch_bounds__(128, 2) attn_h2_kernel()
{
    extern __shared__ __half smh[];
    __half* qh = smh + OQH;  __half* ql = smh + OQL;
    const uint32_t sb = (uint32_t)__cvta_generic_to_shared(smh);

    const int tid  = threadIdx.x;
    const int lane = tid & 31;
    const int wid  = tid >> 5;
    const int g    = lane >> 2;
    const int t    = lane & 3;

    const int qt = (int)gridDim.x - 1 - (int)blockIdx.x;
    const int q0 = qt * 128;
    const int bh_ = blockIdx.y;
    const int b  = bh_ >> 4;
    const int h  = bh_ & 15;

    const size_t base = (size_t)b * SEQ * DIM + h * DH;
    const __half* Qhb = g_Qh + base;  const __half* Qlb = g_Ql + base;
    const __half* Khb = g_Kh + base;  const __half* Klb = g_Kl + base;
    const __half* Vhb = g_Vh + base;  const __half* Vlb = g_Vl + base;

    const int a_r = ((lane >> 3) & 1) * 8 + (lane & 7);
    const int a_c = ((lane >> 4) & 1) * 8;
    const int b_rsel = (lane >> 4);
    const int b_r = (lane & 7);
    const int b_c = ((lane >> 3) & 1) * 8;

    #pragma unroll
    for (int i = 0; i < 16; i++) {
        int pos = tid + i * 128;
        int pl_ = pos >> 10;
        int w   = pos & 1023;
        int row = w >> 3;
        int u   = (w & 7) * 8;
        const __half* src = (pl_ == 0) ? Qhb : Qlb;
        __half* dst = (pl_ == 0) ? qh : ql;
        *(uint4*)&dst[row * AKP + u] = *(const uint4*)(src + (size_t)(q0 + row) * DIM + u);
    }

    auto load_kv = [&](int st, int kvt) {
        const int kv0 = kvt * 64;
        __half* kvbase = smh + OKV0 + st * KVSTG;
        #pragma unroll
        for (int i = 0; i < 16; i++) {
            int uidx = tid + i * 128;
            int p    = uidx >> 9;
            int w    = uidx & 511;
            int row  = w >> 3;
            int u    = (w & 7) * 8;
            const __half* src;
            if (p == 0)      src = Khb;
            else if (p == 1) src = Klb;
            else if (p == 2) src = Vhb;
            else             src = Vlb;
            cp16h(&kvbase[p * 64 * AKP + row * AKP + u],
                  src + (size_t)(kv0 + row) * DIM + u);
        }
    };

    float o[2][8][4];
    float m[4], l[4];
    #pragma unroll
    for (int im = 0; im < 2; im++)
        #pragma unroll
        for (int n = 0; n < 8; n++)
            #pragma unroll
            for (int e = 0; e < 4; e++)
                o[im][n][e] = 0.0f;
    #pragma unroll
    for (int i = 0; i < 4; i++) { m[i] = -INFINITY; l[i] = 0.0f; }

    const int rb  = wid * 32;
    const int wq0 = q0 + rb;
    const int ntiles = 2 * qt + 2;

    load_kv(0, 0);
    cp_commit();

    for (int kvt = 0; kvt < ntiles; kvt++) {
        const int st = kvt & 1;
        const int kv0 = kvt * 64;
        cp_wait<0>();
        __syncthreads();   // copies visible to all; stage st^1 free; Q visible (iter 0)

        const uint32_t kvb = sb + (uint32_t)(OKV0 + st * KVSTG) * 2u;
        const uint32_t khB = kvb;
        const uint32_t klB = kvb + (uint32_t)(64 * AKP) * 2u;
        const uint32_t vhB = kvb + (uint32_t)(2 * 64 * AKP) * 2u;
        const uint32_t vlB = kvb + (uint32_t)(3 * 64 * AKP) * 2u;

        const bool active = (kv0 <= wq0 + 31);
        float s[2][8][4];

        if (active) {
            #pragma unroll
            for (int im = 0; im < 2; im++)
                #pragma unroll
                for (int n = 0; n < 8; n++)
                    #pragma unroll
                    for (int e = 0; e < 4; e++)
                        s[im][n][e] = 0.0f;

            #pragma unroll
            for (int ks = 0; ks < 4; ks++) {
                const int kk = ks * 16;
                uint32_t ahi[2][4], alo[2][4];
                #pragma unroll
                for (int im = 0; im < 2; im++) {
                    uint32_t aoff = (uint32_t)((rb + im * 16 + a_r) * AKP + kk + a_c) * 2u;
                    ldmx4(ahi[im][0], ahi[im][1], ahi[im][2], ahi[im][3],
                          sb + (uint32_t)(OQH * 2) + aoff);
                    ldmx4(alo[im][0], alo[im][1], alo[im][2], alo[im][3],
                          sb + (uint32_t)(OQL * 2) + aoff);
                }
                uint32_t bh[8][2], bl[8][2];
                #pragma unroll
                for (int q = 0; q < 4; q++) {
                    uint32_t boff = (uint32_t)(((2 * q + b_rsel) * 8 + b_r) * AKP
                                               + kk + b_c) * 2u;
                    ldmx4(bh[2*q][0], bh[2*q][1], bh[2*q+1][0], bh[2*q+1][1], khB + boff);
                    ldmx4(bl[2*q][0], bl[2*q][1], bl[2*q+1][0], bl[2*q+1][1], klB + boff);
                }
                #pragma unroll
                for (int im = 0; im < 2; im++)
                    #pragma unroll
                    for (int n = 0; n < 8; n++) {
                        mma16(s[im][n], ahi[im], bh[n]);
                        mma16(s[im][n], ahi[im], bl[n]);
                        mma16(s[im][n], alo[im], bh[n]);
                    }
            }
        }

        // mid-tile prefetch issue (after S-mma, before softmax/PV);
        // still after this tile's barrier -> WAR on stage st^1 safe.
        if (kvt + 1 < ntiles) load_kv(st ^ 1, kvt + 1);
        cp_commit();

        if (active) {
            const bool needmask = (kv0 + 63) > wq0;
            #pragma unroll
            for (int im = 0; im < 2; im++)
                #pragma unroll
                for (int n = 0; n < 8; n++)
                    #pragma unroll
                    for (int e = 0; e < 4; e++) {
                        float v = s[im][n][e] * SCALE_LOG2E;
                        if (needmask) {
                            int col = kv0 + n * 8 + 2 * t + (e & 1);
                            int row = wq0 + im * 16 + g + ((e >> 1) * 8);
                            if (col > row) v = -1e30f;
                        }
                        s[im][n][e] = v;
                    }

            #pragma unroll
            for (int im = 0; im < 2; im++) {
                #pragma unroll
                for (int hh = 0; hh < 2; hh++) {
                    int ri = im * 2 + hh;
                    float rowmax = -INFINITY;
                    #pragma unroll
                    for (int n = 0; n < 8; n++) {
                        rowmax = fmaxf(rowmax, s[im][n][hh * 2 + 0]);
                        rowmax = fmaxf(rowmax, s[im][n][hh * 2 + 1]);
                    }
                    rowmax = fmaxf(rowmax, __shfl_xor_sync(0xffffffffu, rowmax, 1));
                    rowmax = fmaxf(rowmax, __shfl_xor_sync(0xffffffffu, rowmax, 2));
                    float mnew = fmaxf(m[ri], rowmax);
                    float alpha = exp2f(m[ri] - mnew);
                    m[ri] = mnew;
                    float rs = 0.0f;
                    #pragma unroll
                    for (int n = 0; n < 8; n++) {
                        float p0 = exp2f(s[im][n][hh * 2 + 0] - mnew);
                        float p1 = exp2f(s[im][n][hh * 2 + 1] - mnew);
                        s[im][n][hh * 2 + 0] = p0;
                        s[im][n][hh * 2 + 1] = p1;
                        rs += p0 + p1;
                    }
                    rs += __shfl_xor_sync(0xffffffffu, rs, 1);
                    rs += __shfl_xor_sync(0xffffffffu, rs, 2);
                    l[ri] = l[ri] * alpha + rs;
                    #pragma unroll
                    for (int n = 0; n < 8; n++) {
                        o[im][n][hh * 2 + 0] *= alpha;
                        o[im][n][hh * 2 + 1] *= alpha;
                    }
                }
            }

            const int rml = ((lane >> 3) & 1) * 8 + (lane & 7);
            const int cml0 = (lane >> 4) * 8;
            #pragma unroll
            for (int ks = 0; ks < 4; ks++) {
                const int kk = ks * 16;
                uint32_t ahi[2][4], alo[2][4];
                #pragma unroll
                for (int im = 0; im < 2; im++) {
                    __half h0, l0_, h1, l1_;
                    splitf(s[im][2*ks][0] * 256.0f, h0, l0_);
                    splitf(s[im][2*ks][1] * 256.0f, h1, l1_);
                    ahi[im][0] = pack2(h0, h1);  alo[im][0] = pack2(l0_, l1_);
                    splitf(s[im][2*ks][2] * 256.0f, h0, l0_);
                    splitf(s[im][2*ks][3] * 256.0f, h1, l1_);
                    ahi[im][1] = pack2(h0, h1);  alo[im][1] = pack2(l0_, l1_);
                    splitf(s[im][2*ks+1][0] * 256.0f, h0, l0_);
                    splitf(s[im][2*ks+1][1] * 256.0f, h1, l1_);
                    ahi[im][2] = pack2(h0, h1);  alo[im][2] = pack2(l0_, l1_);
                    splitf(s[im][2*ks+1][2] * 256.0f, h0, l0_);
                    splitf(s[im][2*ks+1][3] * 256.0f, h1, l1_);
                    ahi[im][3] = pack2(h0, h1);  alo[im][3] = pack2(l0_, l1_);
                }
                #pragma unroll
                for (int nb = 0; nb < 4; nb++) {
                    uint32_t voff = (uint32_t)((kk + rml) * AKP + nb * 16 + cml0) * 2u;
                    uint32_t h0, h1, h2, h3, l0_, l1_, l2_, l3_;
                    ldmx4t(h0, h1, h2, h3, vhB + voff);
                    ldmx4t(l0_, l1_, l2_, l3_, vlB + voff);
                    uint32_t bh0[2] = { h0, h1 }, bh1[2] = { h2, h3 };
                    uint32_t bl0[2] = { l0_, l1_ }, bl1[2] = { l2_, l3_ };
                    #pragma unroll
                    for (int im = 0; im < 2; im++) {
                        mma16(o[im][2 * nb + 0], ahi[im], bh0);
                        mma16(o[im][2 * nb + 0], ahi[im], bl0);
                        mma16(o[im][2 * nb + 0], alo[im], bh0);
                        mma16(o[im][2 * nb + 1], ahi[im], bh1);
                        mma16(o[im][2 * nb + 1], ahi[im], bl1);
                        mma16(o[im][2 * nb + 1], alo[im], bh1);
                    }
                }
            }
        }
        // no trailing barrier: next iteration's (wait -> sync) provides ordering
    }

    __half* Ohb = g_Oh + base;
    __half* Olb = g_Ol + base;
    #pragma unroll
    for (int im = 0; im < 2; im++) {
        int r0 = q0 + rb + im * 16 + g;
        int r1 = r0 + 8;
        float inv0 = 1.0f / (256.0f * l[im * 2 + 0]);
        float inv1 = 1.0f / (256.0f * l[im * 2 + 1]);
        #pragma unroll
        for (int n = 0; n < 8; n++) {
            int c = n * 8 + 2 * t;
            __half h0, l0_, h1, l1_;
            splitf(o[im][n][0] * inv0, h0, l0_);
            splitf(o[im][n][1] * inv0, h1, l1_);
            *(__half2*)&Ohb[(size_t)r0 * DIM + c] = __halves2half2(h0, h1);
            *(__half2*)&Olb[(size_t)r0 * DIM + c] = __halves2half2(l0_, l1_);
            splitf(o[im][n][2] * inv1, h0, l0_);
            splitf(o[im][n][3] * inv1, h1, l1_);
            *(__half2*)&Ohb[(size_t)r1 * DIM + c] = __halves2half2(h0, h1);
            *(__half2*)&Olb[(size_t)r1 * DIM + c] = __halves2half2(l0_, l1_);
        }
    }
}

// ---------------- launch ----------------
extern "C" void kernel_launch(void* const* d_in, const int* in_sizes, int n_in,
                              void* d_out, int out_size)
{
    const float* x  = (const float*)d_in[0];
    const float* WQ = (const float*)d_in[1];
    const float* WK = (const float*)d_in[2];
    const float* WV = (const float*)d_in[3];
    const float* WO = (const float*)d_in[4];
    const int*  pos = (const int*)d_in[5];
    float* out = (float*)d_out;

    cudaFuncSetAttribute(gemm_h2<true>,  cudaFuncAttributeMaxDynamicSharedMemorySize, GEMM_SMEM);
    cudaFuncSetAttribute(gemm_h2<false>, cudaFuncAttributeMaxDynamicSharedMemorySize, GEMM_SMEM);
    cudaFuncSetAttribute(attn_h2_kernel, cudaFuncAttributeMaxDynamicSharedMemorySize, ATT_SMEM);

    rope_table_kernel<<<(SEQ * 32 + 255) / 256, 256>>>(pos);
    convert_x_kernel<<<(NROWS * DIM / 8 + 255) / 256, 256>>>(x);
    convert_w_all_kernel<<<dim3((DIM * DIM / 8 + 255) / 256, 4), 256>>>(WQ, WK, WV, WO);

    gemm_h2<true><<<dim3(DIM / 128, NROWS / 128, 3), 128, GEMM_SMEM>>>(nullptr);

    attn_h2_kernel<<<dim3(SEQ / 128, BATCH * NHEAD), 128, ATT_SMEM>>>();

    gemm_h2<false><<<dim3(DIM / 128, NROWS / 128, 1), 128, GEMM_SMEM>>>(out);
}